// round 9
// baseline (speedup 1.0000x reference)
#include <cuda_runtime.h>
#include <cuda_bf16.h>
#include <math.h>
#include <stdint.h>

// Problem dims (fixed by the dataset)
#define BQ 64
#define SQ 512
#define DQ 768
#define CQ 512
#define MQ (BQ*SQ)   // 32768 tokens
#define ZCH 8        // s-chunks for partial z

// ---------------- scratch (device globals; no allocation allowed) ----------
// NOTE: these must only be referenced from DEVICE code (host cannot take the
// address of a __device__ symbol) — R8 regression root cause.
__device__ __nv_bfloat16 g_Vn[(size_t)MQ * DQ];   // normalized V, bf16 (48 MB)
__device__ __nv_bfloat16 g_Ln[(size_t)CQ * DQ];   // normalized labels, bf16
__device__ unsigned      g_mkey[MQ];              // ordered-uint encoded row max
__device__ float         g_zpart[BQ * ZCH * DQ];  // partial z sums
__device__ float         g_z[BQ * DQ];            // z vectors

// ordered-uint encoding for float atomicMax (handles negatives)
__device__ __forceinline__ unsigned enc_f(float f) {
    unsigned u = __float_as_uint(f);
    return (u & 0x80000000u) ? ~u : (u | 0x80000000u);
}
__device__ __forceinline__ float dec_f(unsigned u) {
    return (u & 0x80000000u) ? __uint_as_float(u & 0x7fffffffu)
                             : __uint_as_float(~u);
}

// cp.async helpers
__device__ __forceinline__ void cpa16(void* smem, const void* g) {
    unsigned s = (unsigned)__cvta_generic_to_shared(smem);
    asm volatile("cp.async.cg.shared.global [%0], [%1], 16;\n" :: "r"(s), "l"(g));
}
#define CP_COMMIT() asm volatile("cp.async.commit_group;\n" ::: "memory")
#define CP_WAIT(n)  asm volatile("cp.async.wait_group %0;\n" :: "n"(n) : "memory")

__device__ __forceinline__ void ldsm_x4(unsigned& d0, unsigned& d1,
                                        unsigned& d2, unsigned& d3, const void* p) {
    unsigned a = (unsigned)__cvta_generic_to_shared(p);
    asm volatile("ldmatrix.sync.aligned.m8n8.x4.shared.b16 {%0,%1,%2,%3}, [%4];"
                 : "=r"(d0), "=r"(d1), "=r"(d2), "=r"(d3) : "r"(a));
}

// ---------------- kernel 1/3: row-normalize (warp per row) -----------------
// mode 0: labels -> g_Ln ; mode 1: V -> g_Vn   (globals addressed device-side)
__global__ void row_normalize_kernel(const float* __restrict__ in, int nrows, int mode) {
    int gw   = (blockIdx.x * blockDim.x + threadIdx.x) >> 5;
    int lane = threadIdx.x & 31;
    if (gw >= nrows) return;

    const float4* r = (const float4*)(in + (size_t)gw * DQ);
    float4 v[6];
    float ss = 0.f;
#pragma unroll
    for (int i = 0; i < 6; i++) {
        v[i] = r[lane + i * 32];
        ss += v[i].x * v[i].x + v[i].y * v[i].y + v[i].z * v[i].z + v[i].w * v[i].w;
    }
#pragma unroll
    for (int o = 16; o; o >>= 1) ss += __shfl_xor_sync(0xffffffffu, ss, o);
    float sc = 1.0f / fmaxf(sqrtf(ss), 1e-8f);

    __nv_bfloat16* out = (mode ? g_Vn : g_Ln) + (size_t)gw * DQ;
#pragma unroll
    for (int i = 0; i < 6; i++) {
        int base = (lane + i * 32) * 4;
        __nv_bfloat162 p0 = __floats2bfloat162_rn(v[i].x * sc, v[i].y * sc);
        __nv_bfloat162 p1 = __floats2bfloat162_rn(v[i].z * sc, v[i].w * sc);
        uint2 pk;
        pk.x = *(unsigned*)&p0;
        pk.y = *(unsigned*)&p1;
        *(uint2*)(out + base) = pk;
    }
}

// ---------------- kernel 2: init row-max keys ------------------------------
__global__ void mkey_init_kernel() {
    int i = blockIdx.x * blockDim.x + threadIdx.x;
    if (i < MQ) g_mkey[i] = 0u;
}

// ---------------- kernel 4 (profiled): bf16 GEMM + row max -----------------
// EXACT copy of the R7 passing GEMM: CTA 128x128, BK=64, 4 warps (64x64),
// occ 2, 3-stage cp.async, ldmatrix.x4 + register double-buffered fragments.
#define GSTRIDE 72
#define GSTAGE  (128 * GSTRIDE)            // bf16 elems per matrix per stage
#define GK_SMEM (3 * 2 * GSTAGE * 2)       // 110592 bytes

__global__ __launch_bounds__(128, 2)
void gemm_rowmax_kernel() {
    extern __shared__ __nv_bfloat16 sm[];
    __nv_bfloat16* Asm = sm;                 // [3][128][72]
    __nv_bfloat16* Bsm = sm + 3 * GSTAGE;    // [3][128][72]
    __shared__ float rmax[128][2];

    const int bn = blockIdx.x;        // 0..3   (class tiles)
    const int bm = blockIdx.y;        // 0..255 (token tiles)
    const int t = threadIdx.x;        // 128 threads
    const int lane = t & 31, warp = t >> 5;
    const int wr = warp & 1, wc = warp >> 1;
    const int wm0 = wr * 64, wn0 = wc * 64;
    const int g = lane >> 2, tq = lane & 3;
    const int row8 = lane & 7, tile = lane >> 3;
    const int tA_r = (tile & 1) * 8, tA_c = (tile >> 1) * 8;
    const int tB_n = (tile >> 1) * 8, tB_c = (tile & 1) * 8;

    float acc[4][8][4];
#pragma unroll
    for (int mi = 0; mi < 4; mi++)
#pragma unroll
        for (int ni = 0; ni < 8; ni++)
#pragma unroll
            for (int q = 0; q < 4; q++) acc[mi][ni][q] = 0.f;

    const size_t a_base = (size_t)(bm * 128) * DQ;
    const size_t b_base = (size_t)(bn * 128) * DQ;

    auto load_stage = [&](int st, int kt) {
        const int k0 = kt * 64;
        __nv_bfloat16* As = Asm + st * GSTAGE;
        __nv_bfloat16* Bs = Bsm + st * GSTAGE;
#pragma unroll
        for (int i = 0; i < 8; i++) {          // 1024 16B-chunks per matrix
            int idx = t + i * 128;
            int row = idx >> 3, ci = idx & 7;
            cpa16(&As[row * GSTRIDE + ci * 8],
                  &g_Vn[a_base + (size_t)row * DQ + k0 + ci * 8]);
            cpa16(&Bs[row * GSTRIDE + ci * 8],
                  &g_Ln[b_base + (size_t)row * DQ + k0 + ci * 8]);
        }
        CP_COMMIT();
    };

    const int NK = DQ / 64;           // 12
    load_stage(0, 0);
    load_stage(1, 1);

    for (int kt = 0; kt < NK; kt++) {
        const int cur = kt % 3;
        if (kt + 1 < NK) CP_WAIT(1); else CP_WAIT(0);
        __syncthreads();
        if (kt + 2 < NK) load_stage((kt + 2) % 3, kt + 2);

        const __nv_bfloat16* As = Asm + cur * GSTAGE;
        const __nv_bfloat16* Bs = Bsm + cur * GSTAGE;

        unsigned af[2][4][4], bf[2][8][2];
        auto load_frags = [&](int fb, int kk) {
#pragma unroll
            for (int mi = 0; mi < 4; mi++) {
                ldsm_x4(af[fb][mi][0], af[fb][mi][1], af[fb][mi][2], af[fb][mi][3],
                        &As[(wm0 + mi * 16 + tA_r + row8) * GSTRIDE + kk + tA_c]);
            }
#pragma unroll
            for (int ni = 0; ni < 8; ni += 2) {
                ldsm_x4(bf[fb][ni][0], bf[fb][ni][1], bf[fb][ni + 1][0], bf[fb][ni + 1][1],
                        &Bs[(wn0 + ni * 8 + tB_n + row8) * GSTRIDE + kk + tB_c]);
            }
        };

        load_frags(0, 0);
#pragma unroll
        for (int ks = 0; ks < 4; ks++) {
            const int fb = ks & 1;
            if (ks < 3) load_frags(fb ^ 1, (ks + 1) * 16);
#pragma unroll
            for (int mi = 0; mi < 4; mi++)
#pragma unroll
                for (int ni = 0; ni < 8; ni++) {
                    asm volatile(
                        "mma.sync.aligned.m16n8k16.row.col.f32.bf16.bf16.f32 "
                        "{%0,%1,%2,%3}, {%4,%5,%6,%7}, {%8,%9}, {%0,%1,%2,%3};\n"
                        : "+f"(acc[mi][ni][0]), "+f"(acc[mi][ni][1]),
                          "+f"(acc[mi][ni][2]), "+f"(acc[mi][ni][3])
                        : "r"(af[fb][mi][0]), "r"(af[fb][mi][1]),
                          "r"(af[fb][mi][2]), "r"(af[fb][mi][3]),
                          "r"(bf[fb][ni][0]), "r"(bf[fb][ni][1]));
                }
        }
    }

    // per-row max over this 128-class tile
#pragma unroll
    for (int mi = 0; mi < 4; mi++) {
        float lo = -INFINITY, hi = -INFINITY;
#pragma unroll
        for (int ni = 0; ni < 8; ni++) {
            lo = fmaxf(lo, fmaxf(acc[mi][ni][0], acc[mi][ni][1]));
            hi = fmaxf(hi, fmaxf(acc[mi][ni][2], acc[mi][ni][3]));
        }
        lo = fmaxf(lo, __shfl_xor_sync(0xffffffffu, lo, 1));
        lo = fmaxf(lo, __shfl_xor_sync(0xffffffffu, lo, 2));
        hi = fmaxf(hi, __shfl_xor_sync(0xffffffffu, hi, 1));
        hi = fmaxf(hi, __shfl_xor_sync(0xffffffffu, hi, 2));
        if (tq == 0) {
            rmax[wm0 + mi * 16 + g][wc]     = lo;
            rmax[wm0 + mi * 16 + g + 8][wc] = hi;
        }
    }
    __syncthreads();
    if (t < 128) {
        float v = fmaxf(rmax[t][0], rmax[t][1]);
        atomicMax(&g_mkey[bm * 128 + t], enc_f(v));
    }
}

// ---------------- kernel 5: fused softmax + partial z ----------------------
__global__ void zpart_kernel(const float* __restrict__ V) {
    __shared__ float bsm[SQ / ZCH];
    __shared__ float red[8];
    const int b = blockIdx.x, ch = blockIdx.y;
    const int t = threadIdx.x;
    const int lane = t & 31, wid = t >> 5;
    constexpr int RS = SQ / ZCH;   // 64 rows per chunk

    float m0 = dec_f(g_mkey[b * SQ + t]);
    float m1 = dec_f(g_mkey[b * SQ + t + 256]);
    float lm = fmaxf(m0, m1);
#pragma unroll
    for (int o = 16; o; o >>= 1) lm = fmaxf(lm, __shfl_xor_sync(0xffffffffu, lm, o));
    if (lane == 0) red[wid] = lm;
    __syncthreads();
    float M = red[0];
#pragma unroll
    for (int i = 1; i < 8; i++) M = fmaxf(M, red[i]);
    __syncthreads();

    float ls = expf(m0 - M) + expf(m1 - M);
#pragma unroll
    for (int o = 16; o; o >>= 1) ls += __shfl_xor_sync(0xffffffffu, ls, o);
    if (lane == 0) red[wid] = ls;
    __syncthreads();
    float S = 0.f;
#pragma unroll
    for (int i = 0; i < 8; i++) S += red[i];
    float invS = 1.f / S;

    if (t < RS) {
        float mm = dec_f(g_mkey[b * SQ + ch * RS + t]);
        bsm[t] = expf(mm - M) * invS;
    }
    __syncthreads();

    const float* Vb = V + ((size_t)b * SQ + ch * RS) * DQ;
    float a0 = 0.f, a1 = 0.f, a2 = 0.f;
#pragma unroll 4
    for (int r = 0; r < RS; r++) {
        float be = bsm[r];
        const float* row = Vb + (size_t)r * DQ;
        a0 += be * row[t];
        a1 += be * row[t + 256];
        a2 += be * row[t + 512];
    }
    float* zp = g_zpart + (size_t)(b * ZCH + ch) * DQ;
    zp[t]       = a0;
    zp[t + 256] = a1;
    zp[t + 512] = a2;
}

// ---------------- kernel 6: combine partials -> z (float4, high MLP) -------
__global__ void zcombine_kernel(float* __restrict__ zout) {
    const int gi = blockIdx.x * blockDim.x + threadIdx.x;   // 12288 threads
    if (gi >= BQ * DQ / 4) return;
    const int b  = gi / (DQ / 4);
    const int d4 = gi % (DQ / 4);
    float4 s = make_float4(0.f, 0.f, 0.f, 0.f);
#pragma unroll
    for (int c = 0; c < ZCH; c++) {
        float4 p = *(const float4*)&g_zpart[(size_t)(b * ZCH + c) * DQ + d4 * 4];
        s.x += p.x; s.y += p.y; s.z += p.z; s.w += p.w;
    }
    *(float4*)&g_z[b * DQ + d4 * 4] = s;
    if (zout) *(float4*)&zout[b * DQ + d4 * 4] = s;
}

// ---------------- kernel 7: out = z @ fc_w^T + fc_b ------------------------
__global__ void fc_kernel(const float* __restrict__ fc_w, const float* __restrict__ fc_b,
                          float* __restrict__ out) {
    const int t = threadIdx.x;
    const int lane = t & 31;
    const int gw = (blockIdx.x * blockDim.x + t) >> 5;
    if (gw >= BQ * CQ) return;
    const int b = gw >> 9;
    const int c = gw & 511;
    const float4* wr = (const float4*)(fc_w + (size_t)c * DQ);
    const float4* zr = (const float4*)(g_z + b * DQ);
    float acc = 0.f;
#pragma unroll
    for (int i = 0; i < 6; i++) {
        float4 wv = wr[lane + i * 32];
        float4 zv = zr[lane + i * 32];
        acc += wv.x * zv.x + wv.y * zv.y + wv.z * zv.z + wv.w * zv.w;
    }
#pragma unroll
    for (int o = 16; o; o >>= 1) acc += __shfl_xor_sync(0xffffffffu, acc, o);
    if (lane == 0) out[b * CQ + c] = acc + fc_b[c];
}

// ---------------- launch ----------------------------------------------------
extern "C" void kernel_launch(void* const* d_in, const int* in_sizes, int n_in,
                              void* d_out, int out_size) {
    const float* V  = (const float*)d_in[0];
    const float* L  = (const float*)d_in[1];
    const float* fw = (const float*)d_in[2];
    const float* fb = (const float*)d_in[3];
    float* out = (float*)d_out;
    float* zout = (out_size >= BQ * CQ + BQ * DQ) ? (out + BQ * CQ) : nullptr;

    static int smem_set = 0;
    if (!smem_set) {
        cudaFuncSetAttribute(gemm_rowmax_kernel,
                             cudaFuncAttributeMaxDynamicSharedMemorySize, GK_SMEM);
        smem_set = 1;
    }

    // launch order arranged so the GEMM is the 4th launch (ncu profiles #4)
    row_normalize_kernel<<<CQ / 8, 256>>>(L, CQ, 0);                 // 1
    mkey_init_kernel<<<MQ / 256, 256>>>();                           // 2
    row_normalize_kernel<<<MQ / 8, 256>>>(V, MQ, 1);                 // 3
    gemm_rowmax_kernel<<<dim3(CQ / 128, MQ / 128), 128, GK_SMEM>>>(); // 4 (profiled)
    zpart_kernel<<<dim3(BQ, ZCH), 256>>>(V);                         // 5
    zcombine_kernel<<<BQ * DQ / 4 / 256, 256>>>(zout);               // 6
    fc_kernel<<<(BQ * CQ * 32) / 256, 256>>>(fw, fb, out);           // 7
}

// round 10
// speedup vs baseline: 1.1082x; 1.1082x over previous
#include <cuda_runtime.h>
#include <cuda_bf16.h>
#include <math.h>
#include <stdint.h>

// Problem dims (fixed by the dataset)
#define BQ 64
#define SQ 512
#define DQ 768
#define CQ 512
#define MQ (BQ*SQ)   // 32768 tokens
#define ZCH 8        // s-chunks for partial z

// ---------------- scratch (device globals; no allocation allowed) ----------
// Referenced from DEVICE code only (host cannot address __device__ symbols).
__device__ __nv_bfloat16 g_Vn[(size_t)MQ * DQ];   // normalized V, bf16 (48 MB)
__device__ __nv_bfloat16 g_Ln[(size_t)CQ * DQ];   // normalized labels, bf16
__device__ unsigned      g_mkey[MQ];              // ordered-uint encoded row max
__device__ float         g_zpart[BQ * ZCH * DQ];  // partial z sums
__device__ float         g_z[BQ * DQ];            // z vectors

// ordered-uint encoding for float atomicMax (handles negatives)
__device__ __forceinline__ unsigned enc_f(float f) {
    unsigned u = __float_as_uint(f);
    return (u & 0x80000000u) ? ~u : (u | 0x80000000u);
}
__device__ __forceinline__ float dec_f(unsigned u) {
    return (u & 0x80000000u) ? __uint_as_float(u & 0x7fffffffu)
                             : __uint_as_float(~u);
}

// cp.async helpers
__device__ __forceinline__ void cpa16(void* smem, const void* g) {
    unsigned s = (unsigned)__cvta_generic_to_shared(smem);
    asm volatile("cp.async.cg.shared.global [%0], [%1], 16;\n" :: "r"(s), "l"(g));
}
#define CP_COMMIT() asm volatile("cp.async.commit_group;\n" ::: "memory")
#define CP_WAIT(n)  asm volatile("cp.async.wait_group %0;\n" :: "n"(n) : "memory")

__device__ __forceinline__ void ldsm_x4(unsigned& d0, unsigned& d1,
                                        unsigned& d2, unsigned& d3, const void* p) {
    unsigned a = (unsigned)__cvta_generic_to_shared(p);
    asm volatile("ldmatrix.sync.aligned.m8n8.x4.shared.b16 {%0,%1,%2,%3}, [%4];"
                 : "=r"(d0), "=r"(d1), "=r"(d2), "=r"(d3) : "r"(a));
}

// ---------------- kernel 1: init row-max keys (independent) ----------------
__global__ void mkey_init_kernel() {
    int i = blockIdx.x * blockDim.x + threadIdx.x;
    if (i < MQ) g_mkey[i] = 0u;
}

// ---------------- kernel 2: row-normalize V and L in one grid --------------
__global__ void row_normalize_all(const float* __restrict__ V,
                                  const float* __restrict__ L) {
    int gw   = (blockIdx.x * blockDim.x + threadIdx.x) >> 5;
    int lane = threadIdx.x & 31;
    if (gw >= MQ + CQ) return;

    const bool isV = (gw < MQ);
    const float* src = isV ? (V + (size_t)gw * DQ)
                           : (L + (size_t)(gw - MQ) * DQ);
    __nv_bfloat16* out = isV ? (g_Vn + (size_t)gw * DQ)
                             : (g_Ln + (size_t)(gw - MQ) * DQ);

    const float4* r = (const float4*)src;
    float4 v[6];
    float ss = 0.f;
#pragma unroll
    for (int i = 0; i < 6; i++) {
        v[i] = r[lane + i * 32];
        ss += v[i].x * v[i].x + v[i].y * v[i].y + v[i].z * v[i].z + v[i].w * v[i].w;
    }
#pragma unroll
    for (int o = 16; o; o >>= 1) ss += __shfl_xor_sync(0xffffffffu, ss, o);
    float sc = 1.0f / fmaxf(sqrtf(ss), 1e-8f);

#pragma unroll
    for (int i = 0; i < 6; i++) {
        int base = (lane + i * 32) * 4;
        __nv_bfloat162 p0 = __floats2bfloat162_rn(v[i].x * sc, v[i].y * sc);
        __nv_bfloat162 p1 = __floats2bfloat162_rn(v[i].z * sc, v[i].w * sc);
        uint2 pk;
        pk.x = *(unsigned*)&p0;
        pk.y = *(unsigned*)&p1;
        *(uint2*)(out + base) = pk;
    }
}

// ---------------- kernel 3: bf16 GEMM (Vn @ Ln^T) + row max ---------------
// CTA 128x128, BK=64, 4 warps (64x64), occ 2, 3-stage cp.async, ldmatrix.x4
// with register double-buffered fragments. LDSM for k-step 0 issued BEFORE
// the next stage's LDGSTS burst (post-barrier latency overlap).
#define GSTRIDE 72
#define GSTAGE  (128 * GSTRIDE)            // bf16 elems per matrix per stage
#define GK_SMEM (3 * 2 * GSTAGE * 2)       // 110592 bytes

__global__ __launch_bounds__(128, 2)
void gemm_rowmax_kernel() {
    extern __shared__ __nv_bfloat16 sm[];
    __nv_bfloat16* Asm = sm;                 // [3][128][72]
    __nv_bfloat16* Bsm = sm + 3 * GSTAGE;    // [3][128][72]
    __shared__ float rmax[128][2];

    const int bn = blockIdx.x;        // 0..3   (class tiles)
    const int bm = blockIdx.y;        // 0..255 (token tiles)
    const int t = threadIdx.x;        // 128 threads
    const int lane = t & 31, warp = t >> 5;
    const int wr = warp & 1, wc = warp >> 1;
    const int wm0 = wr * 64, wn0 = wc * 64;
    const int g = lane >> 2, tq = lane & 3;
    const int row8 = lane & 7, tile = lane >> 3;
    const int tA_r = (tile & 1) * 8, tA_c = (tile >> 1) * 8;
    const int tB_n = (tile >> 1) * 8, tB_c = (tile & 1) * 8;

    float acc[4][8][4];
#pragma unroll
    for (int mi = 0; mi < 4; mi++)
#pragma unroll
        for (int ni = 0; ni < 8; ni++)
#pragma unroll
            for (int q = 0; q < 4; q++) acc[mi][ni][q] = 0.f;

    const size_t a_base = (size_t)(bm * 128) * DQ;
    const size_t b_base = (size_t)(bn * 128) * DQ;

    auto load_stage = [&](int st, int kt) {
        const int k0 = kt * 64;
        __nv_bfloat16* As = Asm + st * GSTAGE;
        __nv_bfloat16* Bs = Bsm + st * GSTAGE;
#pragma unroll
        for (int i = 0; i < 8; i++) {          // 1024 16B-chunks per matrix
            int idx = t + i * 128;
            int row = idx >> 3, ci = idx & 7;
            cpa16(&As[row * GSTRIDE + ci * 8],
                  &g_Vn[a_base + (size_t)row * DQ + k0 + ci * 8]);
            cpa16(&Bs[row * GSTRIDE + ci * 8],
                  &g_Ln[b_base + (size_t)row * DQ + k0 + ci * 8]);
        }
        CP_COMMIT();
    };

    const int NK = DQ / 64;           // 12
    load_stage(0, 0);
    load_stage(1, 1);

    for (int kt = 0; kt < NK; kt++) {
        const int cur = kt % 3;
        if (kt + 1 < NK) CP_WAIT(1); else CP_WAIT(0);
        __syncthreads();

        const __nv_bfloat16* As = Asm + cur * GSTAGE;
        const __nv_bfloat16* Bs = Bsm + cur * GSTAGE;

        unsigned af[2][4][4], bf[2][8][2];
        auto load_frags = [&](int fb, int kk) {
#pragma unroll
            for (int mi = 0; mi < 4; mi++) {
                ldsm_x4(af[fb][mi][0], af[fb][mi][1], af[fb][mi][2], af[fb][mi][3],
                        &As[(wm0 + mi * 16 + tA_r + row8) * GSTRIDE + kk + tA_c]);
            }
#pragma unroll
            for (int ni = 0; ni < 8; ni += 2) {
                ldsm_x4(bf[fb][ni][0], bf[fb][ni][1], bf[fb][ni + 1][0], bf[fb][ni + 1][1],
                        &Bs[(wn0 + ni * 8 + tB_n + row8) * GSTRIDE + kk + tB_c]);
            }
        };

        // 1) first k-step fragments in flight ASAP after the barrier
        load_frags(0, 0);
        // 2) then the LDGSTS burst for stage kt+2 (overlaps LDSM latency)
        if (kt + 2 < NK) load_stage((kt + 2) % 3, kt + 2);

#pragma unroll
        for (int ks = 0; ks < 4; ks++) {
            const int fb = ks & 1;
            if (ks < 3) load_frags(fb ^ 1, (ks + 1) * 16);
#pragma unroll
            for (int mi = 0; mi < 4; mi++)
#pragma unroll
                for (int ni = 0; ni < 8; ni++) {
                    asm volatile(
                        "mma.sync.aligned.m16n8k16.row.col.f32.bf16.bf16.f32 "
                        "{%0,%1,%2,%3}, {%4,%5,%6,%7}, {%8,%9}, {%0,%1,%2,%3};\n"
                        : "+f"(acc[mi][ni][0]), "+f"(acc[mi][ni][1]),
                          "+f"(acc[mi][ni][2]), "+f"(acc[mi][ni][3])
                        : "r"(af[fb][mi][0]), "r"(af[fb][mi][1]),
                          "r"(af[fb][mi][2]), "r"(af[fb][mi][3]),
                          "r"(bf[fb][ni][0]), "r"(bf[fb][ni][1]));
                }
        }
    }

    // per-row max over this 128-class tile
#pragma unroll
    for (int mi = 0; mi < 4; mi++) {
        float lo = -INFINITY, hi = -INFINITY;
#pragma unroll
        for (int ni = 0; ni < 8; ni++) {
            lo = fmaxf(lo, fmaxf(acc[mi][ni][0], acc[mi][ni][1]));
            hi = fmaxf(hi, fmaxf(acc[mi][ni][2], acc[mi][ni][3]));
        }
        lo = fmaxf(lo, __shfl_xor_sync(0xffffffffu, lo, 1));
        lo = fmaxf(lo, __shfl_xor_sync(0xffffffffu, lo, 2));
        hi = fmaxf(hi, __shfl_xor_sync(0xffffffffu, hi, 1));
        hi = fmaxf(hi, __shfl_xor_sync(0xffffffffu, hi, 2));
        if (tq == 0) {
            rmax[wm0 + mi * 16 + g][wc]     = lo;
            rmax[wm0 + mi * 16 + g + 8][wc] = hi;
        }
    }
    __syncthreads();
    if (t < 128) {
        float v = fmaxf(rmax[t][0], rmax[t][1]);
        atomicMax(&g_mkey[bm * 128 + t], enc_f(v));
    }
}

// ---------------- kernel 4 (profiled): fused softmax + partial z -----------
__global__ void zpart_kernel(const float* __restrict__ V) {
    __shared__ float bsm[SQ / ZCH];
    __shared__ float red[8];
    const int b = blockIdx.x, ch = blockIdx.y;
    const int t = threadIdx.x;
    const int lane = t & 31, wid = t >> 5;
    constexpr int RS = SQ / ZCH;   // 64 rows per chunk

    float m0 = dec_f(g_mkey[b * SQ + t]);
    float m1 = dec_f(g_mkey[b * SQ + t + 256]);
    float lm = fmaxf(m0, m1);
#pragma unroll
    for (int o = 16; o; o >>= 1) lm = fmaxf(lm, __shfl_xor_sync(0xffffffffu, lm, o));
    if (lane == 0) red[wid] = lm;
    __syncthreads();
    float M = red[0];
#pragma unroll
    for (int i = 1; i < 8; i++) M = fmaxf(M, red[i]);
    __syncthreads();

    float ls = expf(m0 - M) + expf(m1 - M);
#pragma unroll
    for (int o = 16; o; o >>= 1) ls += __shfl_xor_sync(0xffffffffu, ls, o);
    if (lane == 0) red[wid] = ls;
    __syncthreads();
    float S = 0.f;
#pragma unroll
    for (int i = 0; i < 8; i++) S += red[i];
    float invS = 1.f / S;

    if (t < RS) {
        float mm = dec_f(g_mkey[b * SQ + ch * RS + t]);
        bsm[t] = expf(mm - M) * invS;
    }
    __syncthreads();

    const float* Vb = V + ((size_t)b * SQ + ch * RS) * DQ;
    float a0 = 0.f, a1 = 0.f, a2 = 0.f;
#pragma unroll 4
    for (int r = 0; r < RS; r++) {
        float be = bsm[r];
        const float* row = Vb + (size_t)r * DQ;
        a0 += be * row[t];
        a1 += be * row[t + 256];
        a2 += be * row[t + 512];
    }
    float* zp = g_zpart + (size_t)(b * ZCH + ch) * DQ;
    zp[t]       = a0;
    zp[t + 256] = a1;
    zp[t + 512] = a2;
}

// ---------------- kernel 5: combine partials -> z (float4, MLP 8) ----------
__global__ void zcombine_kernel(float* __restrict__ zout) {
    const int gi = blockIdx.x * blockDim.x + threadIdx.x;   // 12288 threads
    if (gi >= BQ * DQ / 4) return;
    const int b  = gi / (DQ / 4);
    const int d4 = gi % (DQ / 4);
    float4 s = make_float4(0.f, 0.f, 0.f, 0.f);
#pragma unroll
    for (int c = 0; c < ZCH; c++) {
        float4 p = *(const float4*)&g_zpart[(size_t)(b * ZCH + c) * DQ + d4 * 4];
        s.x += p.x; s.y += p.y; s.z += p.z; s.w += p.w;
    }
    *(float4*)&g_z[b * DQ + d4 * 4] = s;
    if (zout) *(float4*)&zout[b * DQ + d4 * 4] = s;
}

// ---------------- kernel 6: out = z @ fc_w^T + fc_b ------------------------
__global__ void fc_kernel(const float* __restrict__ fc_w, const float* __restrict__ fc_b,
                          float* __restrict__ out) {
    const int t = threadIdx.x;
    const int lane = t & 31;
    const int gw = (blockIdx.x * blockDim.x + t) >> 5;
    if (gw >= BQ * CQ) return;
    const int b = gw >> 9;
    const int c = gw & 511;
    const float4* wr = (const float4*)(fc_w + (size_t)c * DQ);
    const float4* zr = (const float4*)(g_z + b * DQ);
    float acc = 0.f;
#pragma unroll
    for (int i = 0; i < 6; i++) {
        float4 wv = wr[lane + i * 32];
        float4 zv = zr[lane + i * 32];
        acc += wv.x * zv.x + wv.y * zv.y + wv.z * zv.z + wv.w * zv.w;
    }
#pragma unroll
    for (int o = 16; o; o >>= 1) acc += __shfl_xor_sync(0xffffffffu, acc, o);
    if (lane == 0) out[b * CQ + c] = acc + fc_b[c];
}

// ---------------- launch ----------------------------------------------------
extern "C" void kernel_launch(void* const* d_in, const int* in_sizes, int n_in,
                              void* d_out, int out_size) {
    const float* V  = (const float*)d_in[0];
    const float* L  = (const float*)d_in[1];
    const float* fw = (const float*)d_in[2];
    const float* fb = (const float*)d_in[3];
    float* out = (float*)d_out;
    float* zout = (out_size >= BQ * CQ + BQ * DQ) ? (out + BQ * CQ) : nullptr;

    static int smem_set = 0;
    if (!smem_set) {
        cudaFuncSetAttribute(gemm_rowmax_kernel,
                             cudaFuncAttributeMaxDynamicSharedMemorySize, GK_SMEM);
        smem_set = 1;
    }

    // launch #4 = zpart (ncu profiles the 4th launch)
    mkey_init_kernel<<<MQ / 256, 256>>>();                            // 1
    row_normalize_all<<<(MQ + CQ) / 8, 256>>>(V, L);                  // 2
    gemm_rowmax_kernel<<<dim3(CQ / 128, MQ / 128), 128, GK_SMEM>>>(); // 3
    zpart_kernel<<<dim3(BQ, ZCH), 256>>>(V);                          // 4 (profiled)
    zcombine_kernel<<<BQ * DQ / 4 / 256, 256>>>(zout);                // 5
    fc_kernel<<<(BQ * CQ * 32) / 256, 256>>>(fw, fb, out);            // 6
}

// round 12
// speedup vs baseline: 1.1085x; 1.0003x over previous
#include <cuda_runtime.h>
#include <cuda_bf16.h>
#include <math.h>
#include <stdint.h>

// Problem dims (fixed by the dataset)
#define BQ 64
#define SQ 512
#define DQ 768
#define CQ 512
#define MQ (BQ*SQ)   // 32768 tokens
#define ZCH 16       // s-chunks for partial z

// ---------------- scratch (device globals; no allocation allowed) ----------
// Referenced from DEVICE code only (host cannot address __device__ symbols).
__device__ __nv_bfloat16 g_Vn[(size_t)MQ * DQ];   // normalized V, bf16 (48 MB)
__device__ __nv_bfloat16 g_Ln[(size_t)CQ * DQ];   // normalized labels, bf16
__device__ unsigned      g_mkey[MQ];              // ordered-uint encoded row max
__device__ float         g_zpart[BQ * ZCH * DQ];  // partial z sums
__device__ float         g_z[BQ * DQ];            // z vectors

// ordered-uint encoding for float atomicMax (handles negatives)
__device__ __forceinline__ unsigned enc_f(float f) {
    unsigned u = __float_as_uint(f);
    return (u & 0x80000000u) ? ~u : (u | 0x80000000u);
}
__device__ __forceinline__ float dec_f(unsigned u) {
    return (u & 0x80000000u) ? __uint_as_float(u & 0x7fffffffu)
                             : __uint_as_float(~u);
}

// cp.async helpers
__device__ __forceinline__ void cpa16(void* smem, const void* g) {
    unsigned s = (unsigned)__cvta_generic_to_shared(smem);
    asm volatile("cp.async.cg.shared.global [%0], [%1], 16;\n" :: "r"(s), "l"(g));
}
#define CP_COMMIT() asm volatile("cp.async.commit_group;\n" ::: "memory")
#define CP_WAIT(n)  asm volatile("cp.async.wait_group %0;\n" :: "n"(n) : "memory")

__device__ __forceinline__ void ldsm_x4(unsigned& d0, unsigned& d1,
                                        unsigned& d2, unsigned& d3, const void* p) {
    unsigned a = (unsigned)__cvta_generic_to_shared(p);
    asm volatile("ldmatrix.sync.aligned.m8n8.x4.shared.b16 {%0,%1,%2,%3}, [%4];"
                 : "=r"(d0), "=r"(d1), "=r"(d2), "=r"(d3) : "r"(a));
}

// ---------------- kernel 1: init row-max keys ------------------------------
__global__ void mkey_init_kernel() {
    int i = blockIdx.x * blockDim.x + threadIdx.x;
    if (i < MQ) g_mkey[i] = 0u;
}

// ---------------- kernel 2: row-normalize V and L in one grid --------------
__global__ void row_normalize_all(const float* __restrict__ V,
                                  const float* __restrict__ L) {
    int gw   = (blockIdx.x * blockDim.x + threadIdx.x) >> 5;
    int lane = threadIdx.x & 31;
    if (gw >= MQ + CQ) return;

    const bool isV = (gw < MQ);
    const float* src = isV ? (V + (size_t)gw * DQ)
                           : (L + (size_t)(gw - MQ) * DQ);
    __nv_bfloat16* out = isV ? (g_Vn + (size_t)gw * DQ)
                             : (g_Ln + (size_t)(gw - MQ) * DQ);

    const float4* r = (const float4*)src;
    float4 v[6];
    float ss = 0.f;
#pragma unroll
    for (int i = 0; i < 6; i++) {
        v[i] = r[lane + i * 32];
        ss += v[i].x * v[i].x + v[i].y * v[i].y + v[i].z * v[i].z + v[i].w * v[i].w;
    }
#pragma unroll
    for (int o = 16; o; o >>= 1) ss += __shfl_xor_sync(0xffffffffu, ss, o);
    float sc = 1.0f / fmaxf(sqrtf(ss), 1e-8f);

#pragma unroll
    for (int i = 0; i < 6; i++) {
        int base = (lane + i * 32) * 4;
        __nv_bfloat162 p0 = __floats2bfloat162_rn(v[i].x * sc, v[i].y * sc);
        __nv_bfloat162 p1 = __floats2bfloat162_rn(v[i].z * sc, v[i].w * sc);
        uint2 pk;
        pk.x = *(unsigned*)&p0;
        pk.y = *(unsigned*)&p1;
        *(uint2*)(out + base) = pk;
    }
}

// ---------------- kernel 3: bf16 GEMM (Vn @ Ln^T) + row max ---------------
// CTA 128x128, BK=64, 4 warps (64x64), occ 2, 3-stage cp.async, ldmatrix.x4
// register double-buffered fragments; MMA/LDSM interleaved so the tensor
// queue stays fed across k-step boundaries (asm volatile order is final).
#define GSTRIDE 72
#define GSTAGE  (128 * GSTRIDE)            // bf16 elems per matrix per stage
#define GK_SMEM (3 * 2 * GSTAGE * 2)       // 110592 bytes

__global__ __launch_bounds__(128, 2)
void gemm_rowmax_kernel() {
    extern __shared__ __nv_bfloat16 sm[];
    __nv_bfloat16* Asm = sm;                 // [3][128][72]
    __nv_bfloat16* Bsm = sm + 3 * GSTAGE;    // [3][128][72]
    __shared__ float rmax[128][2];

    const int bn = blockIdx.x;        // 0..3   (class tiles)
    const int bm = blockIdx.y;        // 0..255 (token tiles)
    const int t = threadIdx.x;        // 128 threads
    const int lane = t & 31, warp = t >> 5;
    const int wr = warp & 1, wc = warp >> 1;
    const int wm0 = wr * 64, wn0 = wc * 64;
    const int g = lane >> 2, tq = lane & 3;
    const int row8 = lane & 7, tile = lane >> 3;
    const int tA_r = (tile & 1) * 8, tA_c = (tile >> 1) * 8;
    const int tB_n = (tile >> 1) * 8, tB_c = (tile & 1) * 8;

    float acc[4][8][4];
#pragma unroll
    for (int mi = 0; mi < 4; mi++)
#pragma unroll
        for (int ni = 0; ni < 8; ni++)
#pragma unroll
            for (int q = 0; q < 4; q++) acc[mi][ni][q] = 0.f;

    const size_t a_base = (size_t)(bm * 128) * DQ;
    const size_t b_base = (size_t)(bn * 128) * DQ;

    auto load_stage = [&](int st, int kt) {
        const int k0 = kt * 64;
        __nv_bfloat16* As = Asm + st * GSTAGE;
        __nv_bfloat16* Bs = Bsm + st * GSTAGE;
#pragma unroll
        for (int i = 0; i < 8; i++) {          // 1024 16B-chunks per matrix
            int idx = t + i * 128;
            int row = idx >> 3, ci = idx & 7;
            cpa16(&As[row * GSTRIDE + ci * 8],
                  &g_Vn[a_base + (size_t)row * DQ + k0 + ci * 8]);
            cpa16(&Bs[row * GSTRIDE + ci * 8],
                  &g_Ln[b_base + (size_t)row * DQ + k0 + ci * 8]);
        }
        CP_COMMIT();
    };

    const int NK = DQ / 64;           // 12
    load_stage(0, 0);
    load_stage(1, 1);

    for (int kt = 0; kt < NK; kt++) {
        const int cur = kt % 3;
        if (kt + 1 < NK) CP_WAIT(1); else CP_WAIT(0);
        __syncthreads();

        const __nv_bfloat16* As = Asm + cur * GSTAGE;
        const __nv_bfloat16* Bs = Bsm + cur * GSTAGE;

        unsigned af[2][4][4], bf[2][8][2];
        auto load_frags = [&](int fb, int kk) {
#pragma unroll
            for (int mi = 0; mi < 4; mi++) {
                ldsm_x4(af[fb][mi][0], af[fb][mi][1], af[fb][mi][2], af[fb][mi][3],
                        &As[(wm0 + mi * 16 + tA_r + row8) * GSTRIDE + kk + tA_c]);
            }
#pragma unroll
            for (int ni = 0; ni < 8; ni += 2) {
                ldsm_x4(bf[fb][ni][0], bf[fb][ni][1], bf[fb][ni + 1][0], bf[fb][ni + 1][1],
                        &Bs[(wn0 + ni * 8 + tB_n + row8) * GSTRIDE + kk + tB_c]);
            }
        };

        auto mma_half = [&](int fb, int mi0) {
#pragma unroll
            for (int mi = mi0; mi < mi0 + 2; mi++)
#pragma unroll
                for (int ni = 0; ni < 8; ni++) {
                    asm volatile(
                        "mma.sync.aligned.m16n8k16.row.col.f32.bf16.bf16.f32 "
                        "{%0,%1,%2,%3}, {%4,%5,%6,%7}, {%8,%9}, {%0,%1,%2,%3};\n"
                        : "+f"(acc[mi][ni][0]), "+f"(acc[mi][ni][1]),
                          "+f"(acc[mi][ni][2]), "+f"(acc[mi][ni][3])
                        : "r"(af[fb][mi][0]), "r"(af[fb][mi][1]),
                          "r"(af[fb][mi][2]), "r"(af[fb][mi][3]),
                          "r"(bf[fb][ni][0]), "r"(bf[fb][ni][1]));
                }
        };

        // first k-step fragments, then next-stage LDGSTS burst
        load_frags(0, 0);
        if (kt + 2 < NK) load_stage((kt + 2) % 3, kt + 2);

#pragma unroll
        for (int ks = 0; ks < 4; ks++) {
            const int fb = ks & 1;
            mma_half(fb, 0);                              // 16 MMAs feed tensor
            if (ks < 3) load_frags(fb ^ 1, (ks + 1) * 16); // LDSM under MMA latency
            mma_half(fb, 2);                              // 16 more MMAs
        }
    }

    // per-row max over this 128-class tile
#pragma unroll
    for (int mi = 0; mi < 4; mi++) {
        float lo = -INFINITY, hi = -INFINITY;
#pragma unroll
        for (int ni = 0; ni < 8; ni++) {
            lo = fmaxf(lo, fmaxf(acc[mi][ni][0], acc[mi][ni][1]));
            hi = fmaxf(hi, fmaxf(acc[mi][ni][2], acc[mi][ni][3]));
        }
        lo = fmaxf(lo, __shfl_xor_sync(0xffffffffu, lo, 1));
        lo = fmaxf(lo, __shfl_xor_sync(0xffffffffu, lo, 2));
        hi = fmaxf(hi, __shfl_xor_sync(0xffffffffu, hi, 1));
        hi = fmaxf(hi, __shfl_xor_sync(0xffffffffu, hi, 2));
        if (tq == 0) {
            rmax[wm0 + mi * 16 + g][wc]     = lo;
            rmax[wm0 + mi * 16 + g + 8][wc] = hi;
        }
    }
    __syncthreads();
    if (t < 128) {
        float v = fmaxf(rmax[t][0], rmax[t][1]);
        atomicMax(&g_mkey[bm * 128 + t], enc_f(v));
    }
}

// ---------------- kernel 4 (profiled): fused softmax + partial z -----------
// grid (B, ZCH=16), 256 thr; RS=32 rows per CTA.
__global__ void zpart_kernel(const float* __restrict__ V) {
    __shared__ float bsm[SQ / ZCH];
    __shared__ float red[8];
    const int b = blockIdx.x, ch = blockIdx.y;
    const int t = threadIdx.x;
    const int lane = t & 31, wid = t >> 5;
    constexpr int RS = SQ / ZCH;   // 32 rows per chunk

    float m0 = dec_f(g_mkey[b * SQ + t]);
    float m1 = dec_f(g_mkey[b * SQ + t + 256]);
    float lm = fmaxf(m0, m1);
#pragma unroll
    for (int o = 16; o; o >>= 1) lm = fmaxf(lm, __shfl_xor_sync(0xffffffffu, lm, o));
    if (lane == 0) red[wid] = lm;
    __syncthreads();
    float M = red[0];
#pragma unroll
    for (int i = 1; i < 8; i++) M = fmaxf(M, red[i]);
    __syncthreads();

    float ls = expf(m0 - M) + expf(m1 - M);
#pragma unroll
    for (int o = 16; o; o >>= 1) ls += __shfl_xor_sync(0xffffffffu, ls, o);
    if (lane == 0) red[wid] = ls;
    __syncthreads();
    float S = 0.f;
#pragma unroll
    for (int i = 0; i < 8; i++) S += red[i];
    float invS = 1.f / S;

    if (t < RS) {
        float mm = dec_f(g_mkey[b * SQ + ch * RS + t]);
        bsm[t] = expf(mm - M) * invS;
    }
    __syncthreads();

    const float* Vb = V + ((size_t)b * SQ + ch * RS) * DQ;
    float a0 = 0.f, a1 = 0.f, a2 = 0.f;
#pragma unroll 4
    for (int r = 0; r < RS; r++) {
        float be = bsm[r];
        const float* row = Vb + (size_t)r * DQ;
        a0 += be * row[t];
        a1 += be * row[t + 256];
        a2 += be * row[t + 512];
    }
    float* zp = g_zpart + (size_t)(b * ZCH + ch) * DQ;
    zp[t]       = a0;
    zp[t + 256] = a1;
    zp[t + 512] = a2;
}

// ---------------- kernel 5: combine partials -> z (float4, MLP 16) ---------
__global__ void zcombine_kernel(float* __restrict__ zout) {
    const int gi = blockIdx.x * blockDim.x + threadIdx.x;   // 12288 threads
    if (gi >= BQ * DQ / 4) return;
    const int b  = gi / (DQ / 4);
    const int d4 = gi % (DQ / 4);
    float4 s = make_float4(0.f, 0.f, 0.f, 0.f);
#pragma unroll
    for (int c = 0; c < ZCH; c++) {
        float4 p = *(const float4*)&g_zpart[(size_t)(b * ZCH + c) * DQ + d4 * 4];
        s.x += p.x; s.y += p.y; s.z += p.z; s.w += p.w;
    }
    *(float4*)&g_z[b * DQ + d4 * 4] = s;
    if (zout) *(float4*)&zout[b * DQ + d4 * 4] = s;
}

// ---------------- kernel 6: out = z @ fc_w^T + fc_b ------------------------
__global__ void fc_kernel(const float* __restrict__ fc_w, const float* __restrict__ fc_b,
                          float* __restrict__ out) {
    const int t = threadIdx.x;
    const int lane = t & 31;
    const int gw = (blockIdx.x * blockDim.x + t) >> 5;
    if (gw >= BQ * CQ) return;
    const int b = gw >> 9;
    const int c = gw & 511;
    const float4* wr = (const float4*)(fc_w + (size_t)c * DQ);
    const float4* zr = (const float4*)(g_z + b * DQ);
    float acc = 0.f;
#pragma unroll
    for (int i = 0; i < 6; i++) {
        float4 wv = wr[lane + i * 32];
        float4 zv = zr[lane + i * 32];
        acc += wv.x * zv.x + wv.y * zv.y + wv.z * zv.z + wv.w * zv.w;
    }
#pragma unroll
    for (int o = 16; o; o >>= 1) acc += __shfl_xor_sync(0xffffffffu, acc, o);
    if (lane == 0) out[b * CQ + c] = acc + fc_b[c];
}

// ---------------- launch ----------------------------------------------------
extern "C" void kernel_launch(void* const* d_in, const int* in_sizes, int n_in,
                              void* d_out, int out_size) {
    const float* V  = (const float*)d_in[0];
    const float* L  = (const float*)d_in[1];
    const float* fw = (const float*)d_in[2];
    const float* fb = (const float*)d_in[3];
    float* out = (float*)d_out;
    float* zout = (out_size >= BQ * CQ + BQ * DQ) ? (out + BQ * CQ) : nullptr;

    static int smem_set = 0;
    if (!smem_set) {
        cudaFuncSetAttribute(gemm_rowmax_kernel,
                             cudaFuncAttributeMaxDynamicSharedMemorySize, GK_SMEM);
        smem_set = 1;
    }

    mkey_init_kernel<<<MQ / 256, 256>>>();                            // 1
    row_normalize_all<<<(MQ + CQ) / 8, 256>>>(V, L);                  // 2
    gemm_rowmax_kernel<<<dim3(CQ / 128, MQ / 128), 128, GK_SMEM>>>(); // 3
    zpart_kernel<<<dim3(BQ, ZCH), 256>>>(V);                          // 4 (profiled)
    zcombine_kernel<<<BQ * DQ / 4 / 256, 256>>>(zout);                // 5
    fc_kernel<<<(BQ * CQ * 32) / 256, 256>>>(fw, fb, out);            // 6
}

// round 13
// speedup vs baseline: 1.2103x; 1.0919x over previous
#include <cuda_runtime.h>
#include <cuda_bf16.h>
#include <math.h>
#include <stdint.h>

// Problem dims (fixed by the dataset)
#define BQ 64
#define SQ 512
#define DQ 768
#define CQ 512
#define MQ (BQ*SQ)   // 32768 tokens
#define ZCH 16       // s-chunks for partial z

// ---------------- scratch (device globals; no allocation allowed) ----------
// Referenced from DEVICE code only (host cannot address __device__ symbols).
__device__ __nv_bfloat16 g_Vn[(size_t)MQ * DQ];   // normalized V, bf16 (48 MB)
__device__ __nv_bfloat16 g_Ln[(size_t)CQ * DQ];   // normalized labels, bf16
__device__ unsigned      g_mkey[MQ];              // ordered-uint encoded row max
__device__ float         g_zpart[BQ * ZCH * DQ];  // partial z sums
__device__ float         g_z[BQ * DQ];            // z vectors

// ordered-uint encoding for float atomicMax (handles negatives)
__device__ __forceinline__ unsigned enc_f(float f) {
    unsigned u = __float_as_uint(f);
    return (u & 0x80000000u) ? ~u : (u | 0x80000000u);
}
__device__ __forceinline__ float dec_f(unsigned u) {
    return (u & 0x80000000u) ? __uint_as_float(u & 0x7fffffffu)
                             : __uint_as_float(~u);
}

// cp.async helpers
__device__ __forceinline__ void cpa16(void* smem, const void* g) {
    unsigned s = (unsigned)__cvta_generic_to_shared(smem);
    asm volatile("cp.async.cg.shared.global [%0], [%1], 16;\n" :: "r"(s), "l"(g));
}
#define CP_COMMIT() asm volatile("cp.async.commit_group;\n" ::: "memory")
#define CP_WAIT(n)  asm volatile("cp.async.wait_group %0;\n" :: "n"(n) : "memory")

__device__ __forceinline__ void ldsm_x4(unsigned& d0, unsigned& d1,
                                        unsigned& d2, unsigned& d3, const void* p) {
    unsigned a = (unsigned)__cvta_generic_to_shared(p);
    asm volatile("ldmatrix.sync.aligned.m8n8.x4.shared.b16 {%0,%1,%2,%3}, [%4];"
                 : "=r"(d0), "=r"(d1), "=r"(d2), "=r"(d3) : "r"(a));
}

// ---------------- kernel 1: init row-max keys ------------------------------
__global__ void mkey_init_kernel() {
    int i = blockIdx.x * blockDim.x + threadIdx.x;
    if (i < MQ) g_mkey[i] = 0u;
}

// ---------------- kernels 2/3: row-normalize (warp per row) ----------------
// mode 0: labels -> g_Ln ; mode 1: V -> g_Vn   (globals addressed device-side)
__global__ void row_normalize_kernel(const float* __restrict__ in, int nrows, int mode) {
    int gw   = (blockIdx.x * blockDim.x + threadIdx.x) >> 5;
    int lane = threadIdx.x & 31;
    if (gw >= nrows) return;

    const float4* r = (const float4*)(in + (size_t)gw * DQ);
    float4 v[6];
    float ss = 0.f;
#pragma unroll
    for (int i = 0; i < 6; i++) {
        v[i] = r[lane + i * 32];
        ss += v[i].x * v[i].x + v[i].y * v[i].y + v[i].z * v[i].z + v[i].w * v[i].w;
    }
#pragma unroll
    for (int o = 16; o; o >>= 1) ss += __shfl_xor_sync(0xffffffffu, ss, o);
    float sc = 1.0f / fmaxf(sqrtf(ss), 1e-8f);

    __nv_bfloat16* out = (mode ? g_Vn : g_Ln) + (size_t)gw * DQ;
#pragma unroll
    for (int i = 0; i < 6; i++) {
        int base = (lane + i * 32) * 4;
        __nv_bfloat162 p0 = __floats2bfloat162_rn(v[i].x * sc, v[i].y * sc);
        __nv_bfloat162 p1 = __floats2bfloat162_rn(v[i].z * sc, v[i].w * sc);
        uint2 pk;
        pk.x = *(unsigned*)&p0;
        pk.y = *(unsigned*)&p1;
        *(uint2*)(out + base) = pk;
    }
}

// ---------------- kernel 4 (profiled): bf16 GEMM + row max -----------------
// CTA 128x128, BK=64, 4 warps (64x64), occ 2, 3-stage cp.async with the
// 16-LDGSTS stage burst QUARTERED across the 4 k-steps (keeps tensor fed),
// ldmatrix.x4 register double-buffered fragments, MMA/LDSM interleave.
#define GSTRIDE 72
#define GSTAGE  (128 * GSTRIDE)            // bf16 elems per matrix per stage
#define GK_SMEM (3 * 2 * GSTAGE * 2)       // 110592 bytes

__global__ __launch_bounds__(128, 2)
void gemm_rowmax_kernel() {
    extern __shared__ __nv_bfloat16 sm[];
    __nv_bfloat16* Asm = sm;                 // [3][128][72]
    __nv_bfloat16* Bsm = sm + 3 * GSTAGE;    // [3][128][72]
    __shared__ float rmax[128][2];

    const int bn = blockIdx.x;        // 0..3   (class tiles)
    const int bm = blockIdx.y;        // 0..255 (token tiles)
    const int t = threadIdx.x;        // 128 threads
    const int lane = t & 31, warp = t >> 5;
    const int wr = warp & 1, wc = warp >> 1;
    const int wm0 = wr * 64, wn0 = wc * 64;
    const int g = lane >> 2, tq = lane & 3;
    const int row8 = lane & 7, tile = lane >> 3;
    const int tA_r = (tile & 1) * 8, tA_c = (tile >> 1) * 8;
    const int tB_n = (tile >> 1) * 8, tB_c = (tile & 1) * 8;

    float acc[4][8][4];
#pragma unroll
    for (int mi = 0; mi < 4; mi++)
#pragma unroll
        for (int ni = 0; ni < 8; ni++)
#pragma unroll
            for (int q = 0; q < 4; q++) acc[mi][ni][q] = 0.f;

    const size_t a_base = (size_t)(bm * 128) * DQ;
    const size_t b_base = (size_t)(bn * 128) * DQ;

    // 2 chunks (of 8) per call: 2 A + 2 B cp.async
    auto load_stage_part = [&](int st, int ktile, int i0) {
        const int k0 = ktile * 64;
        __nv_bfloat16* As = Asm + st * GSTAGE;
        __nv_bfloat16* Bs = Bsm + st * GSTAGE;
#pragma unroll
        for (int i = i0; i < i0 + 2; i++) {
            int idx = t + i * 128;
            int row = idx >> 3, ci = idx & 7;
            cpa16(&As[row * GSTRIDE + ci * 8],
                  &g_Vn[a_base + (size_t)row * DQ + k0 + ci * 8]);
            cpa16(&Bs[row * GSTRIDE + ci * 8],
                  &g_Ln[b_base + (size_t)row * DQ + k0 + ci * 8]);
        }
    };
    auto load_stage_full = [&](int st, int ktile) {
#pragma unroll
        for (int p = 0; p < 8; p += 2) load_stage_part(st, ktile, p);
        CP_COMMIT();
    };

    const int NK = DQ / 64;           // 12
    load_stage_full(0, 0);
    load_stage_full(1, 1);

    for (int kt = 0; kt < NK; kt++) {
        const int cur = kt % 3;
        if (kt + 1 < NK) CP_WAIT(1); else CP_WAIT(0);
        __syncthreads();

        const __nv_bfloat16* As = Asm + cur * GSTAGE;
        const __nv_bfloat16* Bs = Bsm + cur * GSTAGE;

        unsigned af[2][4][4], bf[2][8][2];
        auto load_frags = [&](int fb, int kk) {
#pragma unroll
            for (int mi = 0; mi < 4; mi++) {
                ldsm_x4(af[fb][mi][0], af[fb][mi][1], af[fb][mi][2], af[fb][mi][3],
                        &As[(wm0 + mi * 16 + tA_r + row8) * GSTRIDE + kk + tA_c]);
            }
#pragma unroll
            for (int ni = 0; ni < 8; ni += 2) {
                ldsm_x4(bf[fb][ni][0], bf[fb][ni][1], bf[fb][ni + 1][0], bf[fb][ni + 1][1],
                        &Bs[(wn0 + ni * 8 + tB_n + row8) * GSTRIDE + kk + tB_c]);
            }
        };

        auto mma_half = [&](int fb, int mi0) {
#pragma unroll
            for (int mi = mi0; mi < mi0 + 2; mi++)
#pragma unroll
                for (int ni = 0; ni < 8; ni++) {
                    asm volatile(
                        "mma.sync.aligned.m16n8k16.row.col.f32.bf16.bf16.f32 "
                        "{%0,%1,%2,%3}, {%4,%5,%6,%7}, {%8,%9}, {%0,%1,%2,%3};\n"
                        : "+f"(acc[mi][ni][0]), "+f"(acc[mi][ni][1]),
                          "+f"(acc[mi][ni][2]), "+f"(acc[mi][ni][3])
                        : "r"(af[fb][mi][0]), "r"(af[fb][mi][1]),
                          "r"(af[fb][mi][2]), "r"(af[fb][mi][3]),
                          "r"(bf[fb][ni][0]), "r"(bf[fb][ni][1]));
                }
        };

        load_frags(0, 0);
        const bool prefetch = (kt + 2 < NK);
        const int nst = (kt + 2) % 3;

#pragma unroll
        for (int ks = 0; ks < 4; ks++) {
            const int fb = ks & 1;
            mma_half(fb, 0);                                   // 16 MMAs
            if (prefetch) load_stage_part(nst, kt + 2, ks * 2); // 4 LDGSTS quarter
            if (ks < 3) load_frags(fb ^ 1, (ks + 1) * 16);      // next frags
            mma_half(fb, 2);                                   // 16 MMAs
        }
        if (prefetch) CP_COMMIT();   // one group per stage (WAIT semantics kept)
    }

    // per-row max over this 128-class tile
#pragma unroll
    for (int mi = 0; mi < 4; mi++) {
        float lo = -INFINITY, hi = -INFINITY;
#pragma unroll
        for (int ni = 0; ni < 8; ni++) {
            lo = fmaxf(lo, fmaxf(acc[mi][ni][0], acc[mi][ni][1]));
            hi = fmaxf(hi, fmaxf(acc[mi][ni][2], acc[mi][ni][3]));
        }
        lo = fmaxf(lo, __shfl_xor_sync(0xffffffffu, lo, 1));
        lo = fmaxf(lo, __shfl_xor_sync(0xffffffffu, lo, 2));
        hi = fmaxf(hi, __shfl_xor_sync(0xffffffffu, hi, 1));
        hi = fmaxf(hi, __shfl_xor_sync(0xffffffffu, hi, 2));
        if (tq == 0) {
            rmax[wm0 + mi * 16 + g][wc]     = lo;
            rmax[wm0 + mi * 16 + g + 8][wc] = hi;
        }
    }
    __syncthreads();
    if (t < 128) {
        float v = fmaxf(rmax[t][0], rmax[t][1]);
        atomicMax(&g_mkey[bm * 128 + t], enc_f(v));
    }
}

// ---------------- kernel 5: fused softmax + partial z (float4, high MLP) ---
// grid (B, ZCH=16), 192 threads; each thread owns ONE float4 column strip.
__global__ void zpart_kernel(const float* __restrict__ V) {
    __shared__ float pbuf[SQ];
    __shared__ float bsm[SQ / ZCH];
    __shared__ float red[6];
    const int b = blockIdx.x, ch = blockIdx.y;
    const int t = threadIdx.x;            // 192
    const int lane = t & 31, wid = t >> 5;
    constexpr int RS = SQ / ZCH;          // 32 rows per chunk

    // load all 512 keys, block max
    float lm = -INFINITY;
    for (int s = t; s < SQ; s += 192) {
        float v = dec_f(g_mkey[b * SQ + s]);
        pbuf[s] = v;
        lm = fmaxf(lm, v);
    }
#pragma unroll
    for (int o = 16; o; o >>= 1) lm = fmaxf(lm, __shfl_xor_sync(0xffffffffu, lm, o));
    if (lane == 0) red[wid] = lm;
    __syncthreads();
    float M = red[0];
#pragma unroll
    for (int i = 1; i < 6; i++) M = fmaxf(M, red[i]);
    __syncthreads();

    float ls = 0.f;
    for (int s = t; s < SQ; s += 192) ls += expf(pbuf[s] - M);
#pragma unroll
    for (int o = 16; o; o >>= 1) ls += __shfl_xor_sync(0xffffffffu, ls, o);
    if (lane == 0) red[wid] = ls;
    __syncthreads();
    float S = 0.f;
#pragma unroll
    for (int i = 0; i < 6; i++) S += red[i];
    float invS = 1.f / S;

    if (t < RS) bsm[t] = expf(pbuf[ch * RS + t] - M) * invS;
    __syncthreads();

    // main: one float4 column per thread, unroll 8 -> 128B in flight/thread
    const float4* Vb = (const float4*)(V + ((size_t)b * SQ + ch * RS) * DQ);
    float4 a = make_float4(0.f, 0.f, 0.f, 0.f);
#pragma unroll 8
    for (int r = 0; r < RS; r++) {
        float be = bsm[r];
        float4 v = Vb[r * (DQ / 4) + t];
        a.x += be * v.x; a.y += be * v.y; a.z += be * v.z; a.w += be * v.w;
    }
    float4* zp = (float4*)(g_zpart + (size_t)(b * ZCH + ch) * DQ);
    zp[t] = a;
}

// ---------------- kernel 6: combine partials -> z (float4, MLP 16) ---------
__global__ void zcombine_kernel(float* __restrict__ zout) {
    const int gi = blockIdx.x * blockDim.x + threadIdx.x;   // 12288 threads
    if (gi >= BQ * DQ / 4) return;
    const int b  = gi / (DQ / 4);
    const int d4 = gi % (DQ / 4);
    float4 s = make_float4(0.f, 0.f, 0.f, 0.f);
#pragma unroll
    for (int c = 0; c < ZCH; c++) {
        float4 p = *(const float4*)&g_zpart[(size_t)(b * ZCH + c) * DQ + d4 * 4];
        s.x += p.x; s.y += p.y; s.z += p.z; s.w += p.w;
    }
    *(float4*)&g_z[b * DQ + d4 * 4] = s;
    if (zout) *(float4*)&zout[b * DQ + d4 * 4] = s;
}

// ---------------- kernel 7: out = z @ fc_w^T + fc_b ------------------------
__global__ void fc_kernel(const float* __restrict__ fc_w, const float* __restrict__ fc_b,
                          float* __restrict__ out) {
    const int t = threadIdx.x;
    const int lane = t & 31;
    const int gw = (blockIdx.x * blockDim.x + t) >> 5;
    if (gw >= BQ * CQ) return;
    const int b = gw >> 9;
    const int c = gw & 511;
    const float4* wr = (const float4*)(fc_w + (size_t)c * DQ);
    const float4* zr = (const float4*)(g_z + b * DQ);
    float acc = 0.f;
#pragma unroll
    for (int i = 0; i < 6; i++) {
        float4 wv = wr[lane + i * 32];
        float4 zv = zr[lane + i * 32];
        acc += wv.x * zv.x + wv.y * zv.y + wv.z * zv.z + wv.w * zv.w;
    }
#pragma unroll
    for (int o = 16; o; o >>= 1) acc += __shfl_xor_sync(0xffffffffu, acc, o);
    if (lane == 0) out[b * CQ + c] = acc + fc_b[c];
}

// ---------------- launch ----------------------------------------------------
extern "C" void kernel_launch(void* const* d_in, const int* in_sizes, int n_in,
                              void* d_out, int out_size) {
    const float* V  = (const float*)d_in[0];
    const float* L  = (const float*)d_in[1];
    const float* fw = (const float*)d_in[2];
    const float* fb = (const float*)d_in[3];
    float* out = (float*)d_out;
    float* zout = (out_size >= BQ * CQ + BQ * DQ) ? (out + BQ * CQ) : nullptr;

    static int smem_set = 0;
    if (!smem_set) {
        cudaFuncSetAttribute(gemm_rowmax_kernel,
                             cudaFuncAttributeMaxDynamicSharedMemorySize, GK_SMEM);
        smem_set = 1;
    }

    // GEMM is launch #4 -> ncu profiles it this round
    mkey_init_kernel<<<MQ / 256, 256>>>();                            // 1
    row_normalize_kernel<<<CQ / 8, 256>>>(L, CQ, 0);                  // 2
    row_normalize_kernel<<<MQ / 8, 256>>>(V, MQ, 1);                  // 3
    gemm_rowmax_kernel<<<dim3(CQ / 128, MQ / 128), 128, GK_SMEM>>>(); // 4 (profiled)
    zpart_kernel<<<dim3(BQ, ZCH), 192>>>(V);                          // 5
    zcombine_kernel<<<BQ * DQ / 4 / 256, 256>>>(zout);                // 6
    fc_kernel<<<(BQ * CQ * 32) / 256, 256>>>(fw, fb, out);            // 7
}

// round 14
// speedup vs baseline: 1.2322x; 1.0181x over previous
#include <cuda_runtime.h>
#include <cuda_bf16.h>
#include <math.h>
#include <stdint.h>

// Problem dims (fixed by the dataset)
#define BQ 64
#define SQ 512
#define DQ 768
#define CQ 512
#define MQ (BQ*SQ)   // 32768 tokens
#define ZCH 16       // s-chunks for partial z

// ---------------- scratch (device globals; no allocation allowed) ----------
// Referenced from DEVICE code only (host cannot address __device__ symbols).
__device__ __nv_bfloat16 g_Vn[(size_t)MQ * DQ];   // normalized V, bf16 (48 MB)
__device__ __nv_bfloat16 g_Ln[(size_t)CQ * DQ];   // normalized labels, bf16
__device__ unsigned      g_mkey[MQ];              // ordered-uint encoded row max
__device__ float         g_zpart[BQ * ZCH * DQ];  // partial z sums
__device__ float         g_z[BQ * DQ];            // z vectors

// ordered-uint encoding for float atomicMax (handles negatives)
__device__ __forceinline__ unsigned enc_f(float f) {
    unsigned u = __float_as_uint(f);
    return (u & 0x80000000u) ? ~u : (u | 0x80000000u);
}
__device__ __forceinline__ float dec_f(unsigned u) {
    return (u & 0x80000000u) ? __uint_as_float(u & 0x7fffffffu)
                             : __uint_as_float(~u);
}

// cp.async helpers
__device__ __forceinline__ void cpa16(void* smem, const void* g) {
    unsigned s = (unsigned)__cvta_generic_to_shared(smem);
    asm volatile("cp.async.cg.shared.global [%0], [%1], 16;\n" :: "r"(s), "l"(g));
}
#define CP_COMMIT() asm volatile("cp.async.commit_group;\n" ::: "memory")
#define CP_WAIT(n)  asm volatile("cp.async.wait_group %0;\n" :: "n"(n) : "memory")

__device__ __forceinline__ void ldsm_x4(unsigned& d0, unsigned& d1,
                                        unsigned& d2, unsigned& d3, const void* p) {
    unsigned a = (unsigned)__cvta_generic_to_shared(p);
    asm volatile("ldmatrix.sync.aligned.m8n8.x4.shared.b16 {%0,%1,%2,%3}, [%4];"
                 : "=r"(d0), "=r"(d1), "=r"(d2), "=r"(d3) : "r"(a));
}

// ---------------- kernel 1: fused init + row-normalize V and L -------------
// rows [0, MQ): V -> g_Vn (+ mkey init); rows [MQ, MQ+CQ): L -> g_Ln
__global__ void norm_init_kernel(const float* __restrict__ V,
                                 const float* __restrict__ L) {
    int gw   = (blockIdx.x * blockDim.x + threadIdx.x) >> 5;
    int lane = threadIdx.x & 31;
    if (gw >= MQ + CQ) return;

    const bool isV = (gw < MQ);
    const float* src = isV ? (V + (size_t)gw * DQ)
                           : (L + (size_t)(gw - MQ) * DQ);
    __nv_bfloat16* out = isV ? (g_Vn + (size_t)gw * DQ)
                             : (g_Ln + (size_t)(gw - MQ) * DQ);

    const float4* r = (const float4*)src;
    float4 v[6];
    float ss = 0.f;
#pragma unroll
    for (int i = 0; i < 6; i++) {
        v[i] = r[lane + i * 32];
        ss += v[i].x * v[i].x + v[i].y * v[i].y + v[i].z * v[i].z + v[i].w * v[i].w;
    }
#pragma unroll
    for (int o = 16; o; o >>= 1) ss += __shfl_xor_sync(0xffffffffu, ss, o);
    float sc = 1.0f / fmaxf(sqrtf(ss), 1e-8f);

#pragma unroll
    for (int i = 0; i < 6; i++) {
        int base = (lane + i * 32) * 4;
        __nv_bfloat162 p0 = __floats2bfloat162_rn(v[i].x * sc, v[i].y * sc);
        __nv_bfloat162 p1 = __floats2bfloat162_rn(v[i].z * sc, v[i].w * sc);
        uint2 pk;
        pk.x = *(unsigned*)&p0;
        pk.y = *(unsigned*)&p1;
        *(uint2*)(out + base) = pk;
    }
    if (isV && lane == 0) g_mkey[gw] = 0u;   // below every encoded real value
}

// ---------------- kernel 2: bf16 GEMM (Vn @ Ln^T) + row max ---------------
// CTA 128x128, BK=64, 4 warps (64x64), occ 2, 3-stage cp.async with the
// 16-LDGSTS stage burst QUARTERED across the 4 k-steps (keeps tensor fed),
// ldmatrix.x4 register double-buffered fragments, MMA/LDSM interleave.
// (byte-identical to the R13 winner)
#define GSTRIDE 72
#define GSTAGE  (128 * GSTRIDE)            // bf16 elems per matrix per stage
#define GK_SMEM (3 * 2 * GSTAGE * 2)       // 110592 bytes

__global__ __launch_bounds__(128, 2)
void gemm_rowmax_kernel() {
    extern __shared__ __nv_bfloat16 sm[];
    __nv_bfloat16* Asm = sm;                 // [3][128][72]
    __nv_bfloat16* Bsm = sm + 3 * GSTAGE;    // [3][128][72]
    __shared__ float rmax[128][2];

    const int bn = blockIdx.x;        // 0..3   (class tiles)
    const int bm = blockIdx.y;        // 0..255 (token tiles)
    const int t = threadIdx.x;        // 128 threads
    const int lane = t & 31, warp = t >> 5;
    const int wr = warp & 1, wc = warp >> 1;
    const int wm0 = wr * 64, wn0 = wc * 64;
    const int g = lane >> 2, tq = lane & 3;
    const int row8 = lane & 7, tile = lane >> 3;
    const int tA_r = (tile & 1) * 8, tA_c = (tile >> 1) * 8;
    const int tB_n = (tile >> 1) * 8, tB_c = (tile & 1) * 8;

    float acc[4][8][4];
#pragma unroll
    for (int mi = 0; mi < 4; mi++)
#pragma unroll
        for (int ni = 0; ni < 8; ni++)
#pragma unroll
            for (int q = 0; q < 4; q++) acc[mi][ni][q] = 0.f;

    const size_t a_base = (size_t)(bm * 128) * DQ;
    const size_t b_base = (size_t)(bn * 128) * DQ;

    auto load_stage_part = [&](int st, int ktile, int i0) {
        const int k0 = ktile * 64;
        __nv_bfloat16* As = Asm + st * GSTAGE;
        __nv_bfloat16* Bs = Bsm + st * GSTAGE;
#pragma unroll
        for (int i = i0; i < i0 + 2; i++) {
            int idx = t + i * 128;
            int row = idx >> 3, ci = idx & 7;
            cpa16(&As[row * GSTRIDE + ci * 8],
                  &g_Vn[a_base + (size_t)row * DQ + k0 + ci * 8]);
            cpa16(&Bs[row * GSTRIDE + ci * 8],
                  &g_Ln[b_base + (size_t)row * DQ + k0 + ci * 8]);
        }
    };
    auto load_stage_full = [&](int st, int ktile) {
#pragma unroll
        for (int p = 0; p < 8; p += 2) load_stage_part(st, ktile, p);
        CP_COMMIT();
    };

    const int NK = DQ / 64;           // 12
    load_stage_full(0, 0);
    load_stage_full(1, 1);

    for (int kt = 0; kt < NK; kt++) {
        const int cur = kt % 3;
        if (kt + 1 < NK) CP_WAIT(1); else CP_WAIT(0);
        __syncthreads();

        const __nv_bfloat16* As = Asm + cur * GSTAGE;
        const __nv_bfloat16* Bs = Bsm + cur * GSTAGE;

        unsigned af[2][4][4], bf[2][8][2];
        auto load_frags = [&](int fb, int kk) {
#pragma unroll
            for (int mi = 0; mi < 4; mi++) {
                ldsm_x4(af[fb][mi][0], af[fb][mi][1], af[fb][mi][2], af[fb][mi][3],
                        &As[(wm0 + mi * 16 + tA_r + row8) * GSTRIDE + kk + tA_c]);
            }
#pragma unroll
            for (int ni = 0; ni < 8; ni += 2) {
                ldsm_x4(bf[fb][ni][0], bf[fb][ni][1], bf[fb][ni + 1][0], bf[fb][ni + 1][1],
                        &Bs[(wn0 + ni * 8 + tB_n + row8) * GSTRIDE + kk + tB_c]);
            }
        };

        auto mma_half = [&](int fb, int mi0) {
#pragma unroll
            for (int mi = mi0; mi < mi0 + 2; mi++)
#pragma unroll
                for (int ni = 0; ni < 8; ni++) {
                    asm volatile(
                        "mma.sync.aligned.m16n8k16.row.col.f32.bf16.bf16.f32 "
                        "{%0,%1,%2,%3}, {%4,%5,%6,%7}, {%8,%9}, {%0,%1,%2,%3};\n"
                        : "+f"(acc[mi][ni][0]), "+f"(acc[mi][ni][1]),
                          "+f"(acc[mi][ni][2]), "+f"(acc[mi][ni][3])
                        : "r"(af[fb][mi][0]), "r"(af[fb][mi][1]),
                          "r"(af[fb][mi][2]), "r"(af[fb][mi][3]),
                          "r"(bf[fb][ni][0]), "r"(bf[fb][ni][1]));
                }
        };

        load_frags(0, 0);
        const bool prefetch = (kt + 2 < NK);
        const int nst = (kt + 2) % 3;

#pragma unroll
        for (int ks = 0; ks < 4; ks++) {
            const int fb = ks & 1;
            mma_half(fb, 0);                                   // 16 MMAs
            if (prefetch) load_stage_part(nst, kt + 2, ks * 2); // 4 LDGSTS quarter
            if (ks < 3) load_frags(fb ^ 1, (ks + 1) * 16);      // next frags
            mma_half(fb, 2);                                   // 16 MMAs
        }
        if (prefetch) CP_COMMIT();   // one group per stage (WAIT semantics kept)
    }

    // per-row max over this 128-class tile
#pragma unroll
    for (int mi = 0; mi < 4; mi++) {
        float lo = -INFINITY, hi = -INFINITY;
#pragma unroll
        for (int ni = 0; ni < 8; ni++) {
            lo = fmaxf(lo, fmaxf(acc[mi][ni][0], acc[mi][ni][1]));
            hi = fmaxf(hi, fmaxf(acc[mi][ni][2], acc[mi][ni][3]));
        }
        lo = fmaxf(lo, __shfl_xor_sync(0xffffffffu, lo, 1));
        lo = fmaxf(lo, __shfl_xor_sync(0xffffffffu, lo, 2));
        hi = fmaxf(hi, __shfl_xor_sync(0xffffffffu, hi, 1));
        hi = fmaxf(hi, __shfl_xor_sync(0xffffffffu, hi, 2));
        if (tq == 0) {
            rmax[wm0 + mi * 16 + g][wc]     = lo;
            rmax[wm0 + mi * 16 + g + 8][wc] = hi;
        }
    }
    __syncthreads();
    if (t < 128) {
        float v = fmaxf(rmax[t][0], rmax[t][1]);
        atomicMax(&g_mkey[bm * 128 + t], enc_f(v));
    }
}

// ---------------- kernel 3: fused softmax + partial z (float4, high MLP) ---
// grid (B, ZCH=16), 192 threads; each thread owns ONE float4 column strip.
__global__ void zpart_kernel(const float* __restrict__ V) {
    __shared__ float pbuf[SQ];
    __shared__ float bsm[SQ / ZCH];
    __shared__ float red[6];
    const int b = blockIdx.x, ch = blockIdx.y;
    const int t = threadIdx.x;            // 192
    const int lane = t & 31, wid = t >> 5;
    constexpr int RS = SQ / ZCH;          // 32 rows per chunk

    float lm = -INFINITY;
    for (int s = t; s < SQ; s += 192) {
        float v = dec_f(g_mkey[b * SQ + s]);
        pbuf[s] = v;
        lm = fmaxf(lm, v);
    }
#pragma unroll
    for (int o = 16; o; o >>= 1) lm = fmaxf(lm, __shfl_xor_sync(0xffffffffu, lm, o));
    if (lane == 0) red[wid] = lm;
    __syncthreads();
    float M = red[0];
#pragma unroll
    for (int i = 1; i < 6; i++) M = fmaxf(M, red[i]);
    __syncthreads();

    float ls = 0.f;
    for (int s = t; s < SQ; s += 192) ls += expf(pbuf[s] - M);
#pragma unroll
    for (int o = 16; o; o >>= 1) ls += __shfl_xor_sync(0xffffffffu, ls, o);
    if (lane == 0) red[wid] = ls;
    __syncthreads();
    float S = 0.f;
#pragma unroll
    for (int i = 0; i < 6; i++) S += red[i];
    float invS = 1.f / S;

    if (t < RS) bsm[t] = expf(pbuf[ch * RS + t] - M) * invS;
    __syncthreads();

    const float4* Vb = (const float4*)(V + ((size_t)b * SQ + ch * RS) * DQ);
    float4 a = make_float4(0.f, 0.f, 0.f, 0.f);
#pragma unroll 8
    for (int r = 0; r < RS; r++) {
        float be = bsm[r];
        float4 v = Vb[r * (DQ / 4) + t];
        a.x += be * v.x; a.y += be * v.y; a.z += be * v.z; a.w += be * v.w;
    }
    float4* zp = (float4*)(g_zpart + (size_t)(b * ZCH + ch) * DQ);
    zp[t] = a;
}

// ---------------- kernel 4: combine partials -> z (float4, MLP 16) ---------
__global__ void zcombine_kernel(float* __restrict__ zout) {
    const int gi = blockIdx.x * blockDim.x + threadIdx.x;   // 12288 threads
    if (gi >= BQ * DQ / 4) return;
    const int b  = gi / (DQ / 4);
    const int d4 = gi % (DQ / 4);
    float4 s = make_float4(0.f, 0.f, 0.f, 0.f);
#pragma unroll
    for (int c = 0; c < ZCH; c++) {
        float4 p = *(const float4*)&g_zpart[(size_t)(b * ZCH + c) * DQ + d4 * 4];
        s.x += p.x; s.y += p.y; s.z += p.z; s.w += p.w;
    }
    *(float4*)&g_z[b * DQ + d4 * 4] = s;
    if (zout) *(float4*)&zout[b * DQ + d4 * 4] = s;
}

// ---------------- kernel 5: out = z @ fc_w^T + fc_b ------------------------
__global__ void fc_kernel(const float* __restrict__ fc_w, const float* __restrict__ fc_b,
                          float* __restrict__ out) {
    const int t = threadIdx.x;
    const int lane = t & 31;
    const int gw = (blockIdx.x * blockDim.x + t) >> 5;
    if (gw >= BQ * CQ) return;
    const int b = gw >> 9;
    const int c = gw & 511;
    const float4* wr = (const float4*)(fc_w + (size_t)c * DQ);
    const float4* zr = (const float4*)(g_z + b * DQ);
    float acc = 0.f;
#pragma unroll
    for (int i = 0; i < 6; i++) {
        float4 wv = wr[lane + i * 32];
        float4 zv = zr[lane + i * 32];
        acc += wv.x * zv.x + wv.y * zv.y + wv.z * zv.z + wv.w * zv.w;
    }
#pragma unroll
    for (int o = 16; o; o >>= 1) acc += __shfl_xor_sync(0xffffffffu, acc, o);
    if (lane == 0) out[b * CQ + c] = acc + fc_b[c];
}

// ---------------- launch ----------------------------------------------------
extern "C" void kernel_launch(void* const* d_in, const int* in_sizes, int n_in,
                              void* d_out, int out_size) {
    const float* V  = (const float*)d_in[0];
    const float* L  = (const float*)d_in[1];
    const float* fw = (const float*)d_in[2];
    const float* fb = (const float*)d_in[3];
    float* out = (float*)d_out;
    float* zout = (out_size >= BQ * CQ + BQ * DQ) ? (out + BQ * CQ) : nullptr;

    static int smem_set = 0;
    if (!smem_set) {
        cudaFuncSetAttribute(gemm_rowmax_kernel,
                             cudaFuncAttributeMaxDynamicSharedMemorySize, GK_SMEM);
        smem_set = 1;
    }

    norm_init_kernel<<<(MQ + CQ) / 8, 256>>>(V, L);                   // 1
    gemm_rowmax_kernel<<<dim3(CQ / 128, MQ / 128), 128, GK_SMEM>>>(); // 2
    zpart_kernel<<<dim3(BQ, ZCH), 192>>>(V);                          // 3
    zcombine_kernel<<<BQ * DQ / 4 / 256, 256>>>(zout);                // 4
    fc_kernel<<<(BQ * CQ * 32) / 256, 256>>>(fw, fb, out);            // 5
}

// round 16
// speedup vs baseline: 1.2716x; 1.0319x over previous
#include <cuda_runtime.h>
#include <cuda_bf16.h>
#include <math.h>
#include <stdint.h>

// Problem dims (fixed by the dataset)
#define BQ 64
#define SQ 512
#define DQ 768
#define CQ 512
#define MQ (BQ*SQ)   // 32768 tokens
#define ZCH 16       // s-chunks for partial z

// ---------------- scratch (device globals; no allocation allowed) ----------
// Referenced from DEVICE code only (host cannot address __device__ symbols).
__device__ __nv_bfloat16 g_Vn[(size_t)MQ * DQ];   // normalized V, bf16 (48 MB)
__device__ __nv_bfloat16 g_Ln[(size_t)CQ * DQ];   // normalized labels, bf16
__device__ unsigned      g_mkey[MQ];              // ordered-uint encoded row max
__device__ float         g_zpart[BQ * ZCH * DQ];  // partial z sums
__device__ float         g_z[BQ * DQ];            // z vectors

// ordered-uint encoding for float atomicMax (handles negatives)
__device__ __forceinline__ unsigned enc_f(float f) {
    unsigned u = __float_as_uint(f);
    return (u & 0x80000000u) ? ~u : (u | 0x80000000u);
}
__device__ __forceinline__ float dec_f(unsigned u) {
    return (u & 0x80000000u) ? __uint_as_float(u & 0x7fffffffu)
                             : __uint_as_float(~u);
}

// cp.async helpers
__device__ __forceinline__ void cpa16(void* smem, const void* g) {
    unsigned s = (unsigned)__cvta_generic_to_shared(smem);
    asm volatile("cp.async.cg.shared.global [%0], [%1], 16;\n" :: "r"(s), "l"(g));
}
#define CP_COMMIT() asm volatile("cp.async.commit_group;\n" ::: "memory")
#define CP_WAIT(n)  asm volatile("cp.async.wait_group %0;\n" :: "n"(n) : "memory")

__device__ __forceinline__ void ldsm_x4(unsigned& d0, unsigned& d1,
                                        unsigned& d2, unsigned& d3, const void* p) {
    unsigned a = (unsigned)__cvta_generic_to_shared(p);
    asm volatile("ldmatrix.sync.aligned.m8n8.x4.shared.b16 {%0,%1,%2,%3}, [%4];"
                 : "=r"(d0), "=r"(d1), "=r"(d2), "=r"(d3) : "r"(a));
}

// ---------------- kernel 1: fused init + row-normalize V and L -------------
// rows [0, MQ): V -> g_Vn (+ mkey init); rows [MQ, MQ+CQ): L -> g_Ln
__global__ void norm_init_kernel(const float* __restrict__ V,
                                 const float* __restrict__ L) {
    int gw   = (blockIdx.x * blockDim.x + threadIdx.x) >> 5;
    int lane = threadIdx.x & 31;
    if (gw >= MQ + CQ) return;

    const bool isV = (gw < MQ);
    const float* src = isV ? (V + (size_t)gw * DQ)
                           : (L + (size_t)(gw - MQ) * DQ);
    __nv_bfloat16* out = isV ? (g_Vn + (size_t)gw * DQ)
                             : (g_Ln + (size_t)(gw - MQ) * DQ);

    const float4* r = (const float4*)src;
    float4 v[6];
    float ss = 0.f;
#pragma unroll
    for (int i = 0; i < 6; i++) {
        v[i] = r[lane + i * 32];
        ss += v[i].x * v[i].x + v[i].y * v[i].y + v[i].z * v[i].z + v[i].w * v[i].w;
    }
#pragma unroll
    for (int o = 16; o; o >>= 1) ss += __shfl_xor_sync(0xffffffffu, ss, o);
    float sc = 1.0f / fmaxf(sqrtf(ss), 1e-8f);

#pragma unroll
    for (int i = 0; i < 6; i++) {
        int base = (lane + i * 32) * 4;
        __nv_bfloat162 p0 = __floats2bfloat162_rn(v[i].x * sc, v[i].y * sc);
        __nv_bfloat162 p1 = __floats2bfloat162_rn(v[i].z * sc, v[i].w * sc);
        uint2 pk;
        pk.x = *(unsigned*)&p0;
        pk.y = *(unsigned*)&p1;
        *(uint2*)(out + base) = pk;
    }
    if (isV && lane == 0) g_mkey[gw] = 0u;   // below every encoded real value
}

// ---------------- kernel 2: bf16 GEMM (Vn @ Ln^T) + row max ---------------
// (byte-identical to the R13 winner)
#define GSTRIDE 72
#define GSTAGE  (128 * GSTRIDE)            // bf16 elems per matrix per stage
#define GK_SMEM (3 * 2 * GSTAGE * 2)       // 110592 bytes

__global__ __launch_bounds__(128, 2)
void gemm_rowmax_kernel() {
    extern __shared__ __nv_bfloat16 sm[];
    __nv_bfloat16* Asm = sm;                 // [3][128][72]
    __nv_bfloat16* Bsm = sm + 3 * GSTAGE;    // [3][128][72]
    __shared__ float rmax[128][2];

    const int bn = blockIdx.x;        // 0..3   (class tiles)
    const int bm = blockIdx.y;        // 0..255 (token tiles)
    const int t = threadIdx.x;        // 128 threads
    const int lane = t & 31, warp = t >> 5;
    const int wr = warp & 1, wc = warp >> 1;
    const int wm0 = wr * 64, wn0 = wc * 64;
    const int g = lane >> 2, tq = lane & 3;
    const int row8 = lane & 7, tile = lane >> 3;
    const int tA_r = (tile & 1) * 8, tA_c = (tile >> 1) * 8;
    const int tB_n = (tile >> 1) * 8, tB_c = (tile & 1) * 8;

    float acc[4][8][4];
#pragma unroll
    for (int mi = 0; mi < 4; mi++)
#pragma unroll
        for (int ni = 0; ni < 8; ni++)
#pragma unroll
            for (int q = 0; q < 4; q++) acc[mi][ni][q] = 0.f;

    const size_t a_base = (size_t)(bm * 128) * DQ;
    const size_t b_base = (size_t)(bn * 128) * DQ;

    auto load_stage_part = [&](int st, int ktile, int i0) {
        const int k0 = ktile * 64;
        __nv_bfloat16* As = Asm + st * GSTAGE;
        __nv_bfloat16* Bs = Bsm + st * GSTAGE;
#pragma unroll
        for (int i = i0; i < i0 + 2; i++) {
            int idx = t + i * 128;
            int row = idx >> 3, ci = idx & 7;
            cpa16(&As[row * GSTRIDE + ci * 8],
                  &g_Vn[a_base + (size_t)row * DQ + k0 + ci * 8]);
            cpa16(&Bs[row * GSTRIDE + ci * 8],
                  &g_Ln[b_base + (size_t)row * DQ + k0 + ci * 8]);
        }
    };
    auto load_stage_full = [&](int st, int ktile) {
#pragma unroll
        for (int p = 0; p < 8; p += 2) load_stage_part(st, ktile, p);
        CP_COMMIT();
    };

    const int NK = DQ / 64;           // 12
    load_stage_full(0, 0);
    load_stage_full(1, 1);

    for (int kt = 0; kt < NK; kt++) {
        const int cur = kt % 3;
        if (kt + 1 < NK) CP_WAIT(1); else CP_WAIT(0);
        __syncthreads();

        const __nv_bfloat16* As = Asm + cur * GSTAGE;
        const __nv_bfloat16* Bs = Bsm + cur * GSTAGE;

        unsigned af[2][4][4], bf[2][8][2];
        auto load_frags = [&](int fb, int kk) {
#pragma unroll
            for (int mi = 0; mi < 4; mi++) {
                ldsm_x4(af[fb][mi][0], af[fb][mi][1], af[fb][mi][2], af[fb][mi][3],
                        &As[(wm0 + mi * 16 + tA_r + row8) * GSTRIDE + kk + tA_c]);
            }
#pragma unroll
            for (int ni = 0; ni < 8; ni += 2) {
                ldsm_x4(bf[fb][ni][0], bf[fb][ni][1], bf[fb][ni + 1][0], bf[fb][ni + 1][1],
                        &Bs[(wn0 + ni * 8 + tB_n + row8) * GSTRIDE + kk + tB_c]);
            }
        };

        auto mma_half = [&](int fb, int mi0) {
#pragma unroll
            for (int mi = mi0; mi < mi0 + 2; mi++)
#pragma unroll
                for (int ni = 0; ni < 8; ni++) {
                    asm volatile(
                        "mma.sync.aligned.m16n8k16.row.col.f32.bf16.bf16.f32 "
                        "{%0,%1,%2,%3}, {%4,%5,%6,%7}, {%8,%9}, {%0,%1,%2,%3};\n"
                        : "+f"(acc[mi][ni][0]), "+f"(acc[mi][ni][1]),
                          "+f"(acc[mi][ni][2]), "+f"(acc[mi][ni][3])
                        : "r"(af[fb][mi][0]), "r"(af[fb][mi][1]),
                          "r"(af[fb][mi][2]), "r"(af[fb][mi][3]),
                          "r"(bf[fb][ni][0]), "r"(bf[fb][ni][1]));
                }
        };

        load_frags(0, 0);
        const bool prefetch = (kt + 2 < NK);
        const int nst = (kt + 2) % 3;

#pragma unroll
        for (int ks = 0; ks < 4; ks++) {
            const int fb = ks & 1;
            mma_half(fb, 0);                                   // 16 MMAs
            if (prefetch) load_stage_part(nst, kt + 2, ks * 2); // 4 LDGSTS quarter
            if (ks < 3) load_frags(fb ^ 1, (ks + 1) * 16);      // next frags
            mma_half(fb, 2);                                   // 16 MMAs
        }
        if (prefetch) CP_COMMIT();   // one group per stage (WAIT semantics kept)
    }

    // per-row max over this 128-class tile
#pragma unroll
    for (int mi = 0; mi < 4; mi++) {
        float lo = -INFINITY, hi = -INFINITY;
#pragma unroll
        for (int ni = 0; ni < 8; ni++) {
            lo = fmaxf(lo, fmaxf(acc[mi][ni][0], acc[mi][ni][1]));
            hi = fmaxf(hi, fmaxf(acc[mi][ni][2], acc[mi][ni][3]));
        }
        lo = fmaxf(lo, __shfl_xor_sync(0xffffffffu, lo, 1));
        lo = fmaxf(lo, __shfl_xor_sync(0xffffffffu, lo, 2));
        hi = fmaxf(hi, __shfl_xor_sync(0xffffffffu, hi, 1));
        hi = fmaxf(hi, __shfl_xor_sync(0xffffffffu, hi, 2));
        if (tq == 0) {
            rmax[wm0 + mi * 16 + g][wc]     = lo;
            rmax[wm0 + mi * 16 + g + 8][wc] = hi;
        }
    }
    __syncthreads();
    if (t < 128) {
        float v = fmaxf(rmax[t][0], rmax[t][1]);
        atomicMax(&g_mkey[bm * 128 + t], enc_f(v));
    }
}

// ---------------- kernel 3: fused softmax + partial z (float4, high MLP) ---
__global__ void zpart_kernel(const float* __restrict__ V) {
    __shared__ float pbuf[SQ];
    __shared__ float bsm[SQ / ZCH];
    __shared__ float red[6];
    const int b = blockIdx.x, ch = blockIdx.y;
    const int t = threadIdx.x;            // 192
    const int lane = t & 31, wid = t >> 5;
    constexpr int RS = SQ / ZCH;          // 32 rows per chunk

    float lm = -INFINITY;
    for (int s = t; s < SQ; s += 192) {
        float v = dec_f(g_mkey[b * SQ + s]);
        pbuf[s] = v;
        lm = fmaxf(lm, v);
    }
#pragma unroll
    for (int o = 16; o; o >>= 1) lm = fmaxf(lm, __shfl_xor_sync(0xffffffffu, lm, o));
    if (lane == 0) red[wid] = lm;
    __syncthreads();
    float M = red[0];
#pragma unroll
    for (int i = 1; i < 6; i++) M = fmaxf(M, red[i]);
    __syncthreads();

    float ls = 0.f;
    for (int s = t; s < SQ; s += 192) ls += expf(pbuf[s] - M);
#pragma unroll
    for (int o = 16; o; o >>= 1) ls += __shfl_xor_sync(0xffffffffu, ls, o);
    if (lane == 0) red[wid] = ls;
    __syncthreads();
    float S = 0.f;
#pragma unroll
    for (int i = 0; i < 6; i++) S += red[i];
    float invS = 1.f / S;

    if (t < RS) bsm[t] = expf(pbuf[ch * RS + t] - M) * invS;
    __syncthreads();

    const float4* Vb = (const float4*)(V + ((size_t)b * SQ + ch * RS) * DQ);
    float4 a = make_float4(0.f, 0.f, 0.f, 0.f);
#pragma unroll 8
    for (int r = 0; r < RS; r++) {
        float be = bsm[r];
        float4 v = Vb[r * (DQ / 4) + t];
        a.x += be * v.x; a.y += be * v.y; a.z += be * v.z; a.w += be * v.w;
    }
    float4* zp = (float4*)(g_zpart + (size_t)(b * ZCH + ch) * DQ);
    zp[t] = a;
}

// ---------------- kernel 4: combine partials -> z (thread/elem, 192 CTAs) --
__global__ void zcombine_kernel(float* __restrict__ zout) {
    const int gi = blockIdx.x * blockDim.x + threadIdx.x;   // 49152 threads
    if (gi >= BQ * DQ) return;
    const int b = gi / DQ;
    const int d = gi % DQ;
    float s = 0.f;
#pragma unroll
    for (int c = 0; c < ZCH; c++) s += g_zpart[(size_t)(b * ZCH + c) * DQ + d];
    g_z[gi] = s;
    if (zout) zout[gi] = s;
}

// ---------------- kernel 5: out = z @ fc_w^T + fc_b ------------------------
// warp per (c, 4 batches): fc_w row loaded once, reused for 4 dots.
__global__ void fc_kernel(const float* __restrict__ fc_w, const float* __restrict__ fc_b,
                          float* __restrict__ out) {
    const int t = threadIdx.x;
    const int lane = t & 31;
    const int gw = (blockIdx.x * blockDim.x + t) >> 5;     // 8192 warps
    if (gw >= CQ * (BQ / 4)) return;
    const int c  = gw & 511;
    const int b0 = (gw >> 9) * 4;

    const float4* wr = (const float4*)(fc_w + (size_t)c * DQ);
    float4 wv[6];
#pragma unroll
    for (int i = 0; i < 6; i++) wv[i] = wr[lane + i * 32];

    float acc0 = 0.f, acc1 = 0.f, acc2 = 0.f, acc3 = 0.f;
#pragma unroll
    for (int i = 0; i < 6; i++) {
        const int idx = lane + i * 32;
        float4 z0 = ((const float4*)(g_z + (size_t)(b0 + 0) * DQ))[idx];
        float4 z1 = ((const float4*)(g_z + (size_t)(b0 + 1) * DQ))[idx];
        float4 z2 = ((const float4*)(g_z + (size_t)(b0 + 2) * DQ))[idx];
        float4 z3 = ((const float4*)(g_z + (size_t)(b0 + 3) * DQ))[idx];
        acc0 += wv[i].x * z0.x + wv[i].y * z0.y + wv[i].z * z0.z + wv[i].w * z0.w;
        acc1 += wv[i].x * z1.x + wv[i].y * z1.y + wv[i].z * z1.z + wv[i].w * z1.w;
        acc2 += wv[i].x * z2.x + wv[i].y * z2.y + wv[i].z * z2.z + wv[i].w * z2.w;
        acc3 += wv[i].x * z3.x + wv[i].y * z3.y + wv[i].z * z3.z + wv[i].w * z3.w;
    }
#pragma unroll
    for (int o = 16; o; o >>= 1) {
        acc0 += __shfl_xor_sync(0xffffffffu, acc0, o);
        acc1 += __shfl_xor_sync(0xffffffffu, acc1, o);
        acc2 += __shfl_xor_sync(0xffffffffu, acc2, o);
        acc3 += __shfl_xor_sync(0xffffffffu, acc3, o);
    }
    if (lane == 0) {
        const float bias = fc_b[c];
        out[(b0 + 0) * CQ + c] = acc0 + bias;
        out[(b0 + 1) * CQ + c] = acc1 + bias;
        out[(b0 + 2) * CQ + c] = acc2 + bias;
        out[(b0 + 3) * CQ + c] = acc3 + bias;
    }
}

// ---------------- launch ----------------------------------------------------
extern "C" void kernel_launch(void* const* d_in, const int* in_sizes, int n_in,
                              void* d_out, int out_size) {
    const float* V  = (const float*)d_in[0];
    const float* L  = (const float*)d_in[1];
    const float* fw = (const float*)d_in[2];
    const float* fb = (const float*)d_in[3];
    float* out = (float*)d_out;
    float* zout = (out_size >= BQ * CQ + BQ * DQ) ? (out + BQ * CQ) : nullptr;

    static int smem_set = 0;
    if (!smem_set) {
        cudaFuncSetAttribute(gemm_rowmax_kernel,
                             cudaFuncAttributeMaxDynamicSharedMemorySize, GK_SMEM);
        smem_set = 1;
    }

    norm_init_kernel<<<(MQ + CQ) / 8, 256>>>(V, L);                   // 1
    gemm_rowmax_kernel<<<dim3(CQ / 128, MQ / 128), 128, GK_SMEM>>>(); // 2
    zpart_kernel<<<dim3(BQ, ZCH), 192>>>(V);                          // 3
    zcombine_kernel<<<BQ * DQ / 256, 256>>>(zout);                    // 4
    fc_kernel<<<(CQ * (BQ / 4) * 32) / 256, 256>>>(fw, fb, out);      // 5
}

// round 17
// speedup vs baseline: 1.2984x; 1.0211x over previous
#include <cuda_runtime.h>
#include <cuda_bf16.h>
#include <math.h>
#include <stdint.h>

// Problem dims (fixed by the dataset)
#define BQ 64
#define SQ 512
#define DQ 768
#define CQ 512
#define MQ (BQ*SQ)   // 32768 tokens
#define ZCH 16       // s-chunks for partial z

// ---------------- scratch (device globals; no allocation allowed) ----------
// Referenced from DEVICE code only (host cannot address __device__ symbols).
__device__ __nv_bfloat16 g_Vn[(size_t)MQ * DQ];   // normalized V, bf16 (48 MB)
__device__ __nv_bfloat16 g_Ln[(size_t)CQ * DQ];   // normalized labels, bf16
__device__ unsigned      g_mkey[MQ];              // ordered-uint encoded row max
__device__ float         g_zpart[BQ * ZCH * DQ];  // partial z sums
__device__ float         g_z[BQ * DQ];            // z vectors

// ordered-uint encoding for float atomicMax (handles negatives)
__device__ __forceinline__ unsigned enc_f(float f) {
    unsigned u = __float_as_uint(f);
    return (u & 0x80000000u) ? ~u : (u | 0x80000000u);
}
__device__ __forceinline__ float dec_f(unsigned u) {
    return (u & 0x80000000u) ? __uint_as_float(u & 0x7fffffffu)
                             : __uint_as_float(~u);
}

// cp.async helpers
__device__ __forceinline__ void cpa16(void* smem, const void* g) {
    unsigned s = (unsigned)__cvta_generic_to_shared(smem);
    asm volatile("cp.async.cg.shared.global [%0], [%1], 16;\n" :: "r"(s), "l"(g));
}
#define CP_COMMIT() asm volatile("cp.async.commit_group;\n" ::: "memory")
#define CP_WAIT(n)  asm volatile("cp.async.wait_group %0;\n" :: "n"(n) : "memory")

__device__ __forceinline__ void ldsm_x4(unsigned& d0, unsigned& d1,
                                        unsigned& d2, unsigned& d3, const void* p) {
    unsigned a = (unsigned)__cvta_generic_to_shared(p);
    asm volatile("ldmatrix.sync.aligned.m8n8.x4.shared.b16 {%0,%1,%2,%3}, [%4];"
                 : "=r"(d0), "=r"(d1), "=r"(d2), "=r"(d3) : "r"(a));
}

// ---------------- kernel 1: fused init + row-normalize V and L -------------
__global__ void norm_init_kernel(const float* __restrict__ V,
                                 const float* __restrict__ L) {
    int gw   = (blockIdx.x * blockDim.x + threadIdx.x) >> 5;
    int lane = threadIdx.x & 31;
    if (gw >= MQ + CQ) return;

    const bool isV = (gw < MQ);
    const float* src = isV ? (V + (size_t)gw * DQ)
                           : (L + (size_t)(gw - MQ) * DQ);
    __nv_bfloat16* out = isV ? (g_Vn + (size_t)gw * DQ)
                             : (g_Ln + (size_t)(gw - MQ) * DQ);

    const float4* r = (const float4*)src;
    float4 v[6];
    float ss = 0.f;
#pragma unroll
    for (int i = 0; i < 6; i++) {
        v[i] = r[lane + i * 32];
        ss += v[i].x * v[i].x + v[i].y * v[i].y + v[i].z * v[i].z + v[i].w * v[i].w;
    }
#pragma unroll
    for (int o = 16; o; o >>= 1) ss += __shfl_xor_sync(0xffffffffu, ss, o);
    float sc = 1.0f / fmaxf(sqrtf(ss), 1e-8f);

#pragma unroll
    for (int i = 0; i < 6; i++) {
        int base = (lane + i * 32) * 4;
        __nv_bfloat162 p0 = __floats2bfloat162_rn(v[i].x * sc, v[i].y * sc);
        __nv_bfloat162 p1 = __floats2bfloat162_rn(v[i].z * sc, v[i].w * sc);
        uint2 pk;
        pk.x = *(unsigned*)&p0;
        pk.y = *(unsigned*)&p1;
        *(uint2*)(out + base) = pk;
    }
    if (isV && lane == 0) g_mkey[gw] = 0u;   // below every encoded real value
}

// ---------------- kernel 2: bf16 GEMM (Vn @ Ln^T) + row max ---------------
// CTA 128x128, BK=64, 4 warps (64x64), occ 2, 3-stage cp.async.
// FINE BRAID: each k-step = 8MMA | 4 LDGSTS | 8MMA | A-LDSM | 8MMA | B-LDSM | 8MMA
#define GSTRIDE 72
#define GSTAGE  (128 * GSTRIDE)            // bf16 elems per matrix per stage
#define GK_SMEM (3 * 2 * GSTAGE * 2)       // 110592 bytes

__global__ __launch_bounds__(128, 2)
void gemm_rowmax_kernel() {
    extern __shared__ __nv_bfloat16 sm[];
    __nv_bfloat16* Asm = sm;                 // [3][128][72]
    __nv_bfloat16* Bsm = sm + 3 * GSTAGE;    // [3][128][72]
    __shared__ float rmax[128][2];

    const int bn = blockIdx.x;        // 0..3   (class tiles)
    const int bm = blockIdx.y;        // 0..255 (token tiles)
    const int t = threadIdx.x;        // 128 threads
    const int lane = t & 31, warp = t >> 5;
    const int wr = warp & 1, wc = warp >> 1;
    const int wm0 = wr * 64, wn0 = wc * 64;
    const int g = lane >> 2, tq = lane & 3;
    const int row8 = lane & 7, tile = lane >> 3;
    const int tA_r = (tile & 1) * 8, tA_c = (tile >> 1) * 8;
    const int tB_n = (tile >> 1) * 8, tB_c = (tile & 1) * 8;

    float acc[4][8][4];
#pragma unroll
    for (int mi = 0; mi < 4; mi++)
#pragma unroll
        for (int ni = 0; ni < 8; ni++)
#pragma unroll
            for (int q = 0; q < 4; q++) acc[mi][ni][q] = 0.f;

    const size_t a_base = (size_t)(bm * 128) * DQ;
    const size_t b_base = (size_t)(bn * 128) * DQ;

    auto load_stage_part = [&](int st, int ktile, int i0) {
        const int k0 = ktile * 64;
        __nv_bfloat16* As = Asm + st * GSTAGE;
        __nv_bfloat16* Bs = Bsm + st * GSTAGE;
#pragma unroll
        for (int i = i0; i < i0 + 2; i++) {
            int idx = t + i * 128;
            int row = idx >> 3, ci = idx & 7;
            cpa16(&As[row * GSTRIDE + ci * 8],
                  &g_Vn[a_base + (size_t)row * DQ + k0 + ci * 8]);
            cpa16(&Bs[row * GSTRIDE + ci * 8],
                  &g_Ln[b_base + (size_t)row * DQ + k0 + ci * 8]);
        }
    };
    auto load_stage_full = [&](int st, int ktile) {
#pragma unroll
        for (int p = 0; p < 8; p += 2) load_stage_part(st, ktile, p);
        CP_COMMIT();
    };

    const int NK = DQ / 64;           // 12
    load_stage_full(0, 0);
    load_stage_full(1, 1);

    for (int kt = 0; kt < NK; kt++) {
        const int cur = kt % 3;
        if (kt + 1 < NK) CP_WAIT(1); else CP_WAIT(0);
        __syncthreads();

        const __nv_bfloat16* As = Asm + cur * GSTAGE;
        const __nv_bfloat16* Bs = Bsm + cur * GSTAGE;

        unsigned af[2][4][4], bf[2][8][2];
        auto frags_A = [&](int fb, int kk) {
#pragma unroll
            for (int mi = 0; mi < 4; mi++) {
                ldsm_x4(af[fb][mi][0], af[fb][mi][1], af[fb][mi][2], af[fb][mi][3],
                        &As[(wm0 + mi * 16 + tA_r + row8) * GSTRIDE + kk + tA_c]);
            }
        };
        auto frags_B = [&](int fb, int kk) {
#pragma unroll
            for (int ni = 0; ni < 8; ni += 2) {
                ldsm_x4(bf[fb][ni][0], bf[fb][ni][1], bf[fb][ni + 1][0], bf[fb][ni + 1][1],
                        &Bs[(wn0 + ni * 8 + tB_n + row8) * GSTRIDE + kk + tB_c]);
            }
        };

        auto mma_q = [&](int fb, int mi) {   // 8 MMAs: one mi row
#pragma unroll
            for (int ni = 0; ni < 8; ni++) {
                asm volatile(
                    "mma.sync.aligned.m16n8k16.row.col.f32.bf16.bf16.f32 "
                    "{%0,%1,%2,%3}, {%4,%5,%6,%7}, {%8,%9}, {%0,%1,%2,%3};\n"
                    : "+f"(acc[mi][ni][0]), "+f"(acc[mi][ni][1]),
                      "+f"(acc[mi][ni][2]), "+f"(acc[mi][ni][3])
                    : "r"(af[fb][mi][0]), "r"(af[fb][mi][1]),
                      "r"(af[fb][mi][2]), "r"(af[fb][mi][3]),
                      "r"(bf[fb][ni][0]), "r"(bf[fb][ni][1]));
            }
        };

        frags_A(0, 0);
        frags_B(0, 0);
        const bool prefetch = (kt + 2 < NK);
        const int nst = (kt + 2) % 3;

#pragma unroll
        for (int ks = 0; ks < 4; ks++) {
            const int fb = ks & 1;
            mma_q(fb, 0);                                       // 8 MMA
            if (prefetch) load_stage_part(nst, kt + 2, ks * 2); // 4 LDGSTS
            mma_q(fb, 1);                                       // 8 MMA
            if (ks < 3) frags_A(fb ^ 1, (ks + 1) * 16);         // 4 LDSM
            mma_q(fb, 2);                                       // 8 MMA
            if (ks < 3) frags_B(fb ^ 1, (ks + 1) * 16);         // 4 LDSM
            mma_q(fb, 3);                                       // 8 MMA
        }
        if (prefetch) CP_COMMIT();   // one group per stage (WAIT semantics kept)
    }

    // per-row max over this 128-class tile
#pragma unroll
    for (int mi = 0; mi < 4; mi++) {
        float lo = -INFINITY, hi = -INFINITY;
#pragma unroll
        for (int ni = 0; ni < 8; ni++) {
            lo = fmaxf(lo, fmaxf(acc[mi][ni][0], acc[mi][ni][1]));
            hi = fmaxf(hi, fmaxf(acc[mi][ni][2], acc[mi][ni][3]));
        }
        lo = fmaxf(lo, __shfl_xor_sync(0xffffffffu, lo, 1));
        lo = fmaxf(lo, __shfl_xor_sync(0xffffffffu, lo, 2));
        hi = fmaxf(hi, __shfl_xor_sync(0xffffffffu, hi, 1));
        hi = fmaxf(hi, __shfl_xor_sync(0xffffffffu, hi, 2));
        if (tq == 0) {
            rmax[wm0 + mi * 16 + g][wc]     = lo;
            rmax[wm0 + mi * 16 + g + 8][wc] = hi;
        }
    }
    __syncthreads();
    if (t < 128) {
        float v = fmaxf(rmax[t][0], rmax[t][1]);
        atomicMax(&g_mkey[bm * 128 + t], enc_f(v));
    }
}

// ---------------- kernel 3: fused softmax + partial z (float4, high MLP) ---
__global__ void zpart_kernel(const float* __restrict__ V) {
    __shared__ float pbuf[SQ];
    __shared__ float bsm[SQ / ZCH];
    __shared__ float red[6];
    const int b = blockIdx.x, ch = blockIdx.y;
    const int t = threadIdx.x;            // 192
    const int lane = t & 31, wid = t >> 5;
    constexpr int RS = SQ / ZCH;          // 32 rows per chunk

    float lm = -INFINITY;
    for (int s = t; s < SQ; s += 192) {
        float v = dec_f(g_mkey[b * SQ + s]);
        pbuf[s] = v;
        lm = fmaxf(lm, v);
    }
#pragma unroll
    for (int o = 16; o; o >>= 1) lm = fmaxf(lm, __shfl_xor_sync(0xffffffffu, lm, o));
    if (lane == 0) red[wid] = lm;
    __syncthreads();
    float M = red[0];
#pragma unroll
    for (int i = 1; i < 6; i++) M = fmaxf(M, red[i]);
    __syncthreads();

    float ls = 0.f;
    for (int s = t; s < SQ; s += 192) ls += expf(pbuf[s] - M);
#pragma unroll
    for (int o = 16; o; o >>= 1) ls += __shfl_xor_sync(0xffffffffu, ls, o);
    if (lane == 0) red[wid] = ls;
    __syncthreads();
    float S = 0.f;
#pragma unroll
    for (int i = 0; i < 6; i++) S += red[i];
    float invS = 1.f / S;

    if (t < RS) bsm[t] = expf(pbuf[ch * RS + t] - M) * invS;
    __syncthreads();

    const float4* Vb = (const float4*)(V + ((size_t)b * SQ + ch * RS) * DQ);
    float4 a = make_float4(0.f, 0.f, 0.f, 0.f);
#pragma unroll 8
    for (int r = 0; r < RS; r++) {
        float be = bsm[r];
        float4 v = Vb[r * (DQ / 4) + t];
        a.x += be * v.x; a.y += be * v.y; a.z += be * v.z; a.w += be * v.w;
    }
    float4* zp = (float4*)(g_zpart + (size_t)(b * ZCH + ch) * DQ);
    zp[t] = a;
}

// ---------------- kernel 4: combine partials -> z (2 threads per element) --
// 384 CTAs x 256 thr; threads t and t+128 split the 16 partials of element
// (blockIdx*128 + t&127), pair-combined through shared memory.
__global__ void zcombine_kernel(float* __restrict__ zout) {
    __shared__ float buf[128];
    const int e  = threadIdx.x & 127;
    const int hf = threadIdx.x >> 7;              // 0 or 1
    const int gi = blockIdx.x * 128 + e;          // element id in [0, BQ*DQ)
    const int b  = gi / DQ;
    const int d  = gi % DQ;

    float s = 0.f;
#pragma unroll
    for (int c = 0; c < ZCH / 2; c++)
        s += g_zpart[(size_t)(b * ZCH + hf * (ZCH / 2) + c) * DQ + d];

    if (hf) buf[e] = s;
    __syncthreads();
    if (!hf) {
        s += buf[e];
        g_z[gi] = s;
        if (zout) zout[gi] = s;
    }
}

// ---------------- kernel 5: out = z @ fc_w^T + fc_b ------------------------
// warp per (c, 4 batches): fc_w row loaded once, reused for 4 dots.
__global__ void fc_kernel(const float* __restrict__ fc_w, const float* __restrict__ fc_b,
                          float* __restrict__ out) {
    const int t = threadIdx.x;
    const int lane = t & 31;
    const int gw = (blockIdx.x * blockDim.x + t) >> 5;     // 8192 warps
    if (gw >= CQ * (BQ / 4)) return;
    const int c  = gw & 511;
    const int b0 = (gw >> 9) * 4;

    const float4* wr = (const float4*)(fc_w + (size_t)c * DQ);
    float4 wv[6];
#pragma unroll
    for (int i = 0; i < 6; i++) wv[i] = wr[lane + i * 32];

    float acc0 = 0.f, acc1 = 0.f, acc2 = 0.f, acc3 = 0.f;
#pragma unroll
    for (int i = 0; i < 6; i++) {
        const int idx = lane + i * 32;
        float4 z0 = ((const float4*)(g_z + (size_t)(b0 + 0) * DQ))[idx];
        float4 z1 = ((const float4*)(g_z + (size_t)(b0 + 1) * DQ))[idx];
        float4 z2 = ((const float4*)(g_z + (size_t)(b0 + 2) * DQ))[idx];
        float4 z3 = ((const float4*)(g_z + (size_t)(b0 + 3) * DQ))[idx];
        acc0 += wv[i].x * z0.x + wv[i].y * z0.y + wv[i].z * z0.z + wv[i].w * z0.w;
        acc1 += wv[i].x * z1.x + wv[i].y * z1.y + wv[i].z * z1.z + wv[i].w * z1.w;
        acc2 += wv[i].x * z2.x + wv[i].y * z2.y + wv[i].z * z2.z + wv[i].w * z2.w;
        acc3 += wv[i].x * z3.x + wv[i].y * z3.y + wv[i].z * z3.z + wv[i].w * z3.w;
    }
#pragma unroll
    for (int o = 16; o; o >>= 1) {
        acc0 += __shfl_xor_sync(0xffffffffu, acc0, o);
        acc1 += __shfl_xor_sync(0xffffffffu, acc1, o);
        acc2 += __shfl_xor_sync(0xffffffffu, acc2, o);
        acc3 += __shfl_xor_sync(0xffffffffu, acc3, o);
    }
    if (lane == 0) {
        const float bias = fc_b[c];
        out[(b0 + 0) * CQ + c] = acc0 + bias;
        out[(b0 + 1) * CQ + c] = acc1 + bias;
        out[(b0 + 2) * CQ + c] = acc2 + bias;
        out[(b0 + 3) * CQ + c] = acc3 + bias;
    }
}

// ---------------- launch ----------------------------------------------------
extern "C" void kernel_launch(void* const* d_in, const int* in_sizes, int n_in,
                              void* d_out, int out_size) {
    const float* V  = (const float*)d_in[0];
    const float* L  = (const float*)d_in[1];
    const float* fw = (const float*)d_in[2];
    const float* fb = (const float*)d_in[3];
    float* out = (float*)d_out;
    float* zout = (out_size >= BQ * CQ + BQ * DQ) ? (out + BQ * CQ) : nullptr;

    static int smem_set = 0;
    if (!smem_set) {
        cudaFuncSetAttribute(gemm_rowmax_kernel,
                             cudaFuncAttributeMaxDynamicSharedMemorySize, GK_SMEM);
        smem_set = 1;
    }

    norm_init_kernel<<<(MQ + CQ) / 8, 256>>>(V, L);                   // 1
    gemm_rowmax_kernel<<<dim3(CQ / 128, MQ / 128), 128, GK_SMEM>>>(); // 2
    zpart_kernel<<<dim3(BQ, ZCH), 192>>>(V);                          // 3
    zcombine_kernel<<<BQ * DQ / 128, 256>>>(zout);                    // 4
    fc_kernel<<<(CQ * (BQ / 4) * 32) / 256, 256>>>(fw, fb, out);      // 5
}